// round 14
// baseline (speedup 1.0000x reference)
#include <cuda_runtime.h>
#include <cstdint>
#include <math.h>

#define BB 8
#define LDQ 512
#define DIM 512
#define NH 8
#define FFD 2048
#define NLAY 6

// ---------------- scratch (static device globals; no allocation) ----------------
__device__ float g_x[BB * LDQ * DIM];
__device__ float g_xr[BB * LDQ * DIM];
__device__ float g_encr[BB * LDQ * DIM];
__device__ float g_q[BB * LDQ * DIM];
__device__ float g_k[BB * LDQ * DIM];
__device__ float g_vt[DIM * BB * LDQ];
__device__ float g_ctx[BB * LDQ * DIM];
__device__ float g_proj[BB * LDQ * DIM];
__device__ float g_ffh[BB * LDQ * FFD];
__device__ float g_wr[8 * NLAY * DIM * DIM];
__device__ float g_w1r[NLAY * FFD * DIM];
__device__ float g_w2r[NLAY * DIM * FFD];
__device__ float g_kca[NLAY * BB * LDQ * DIM];
__device__ float g_vtca[NLAY * DIM * BB * LDQ];

// ---------------- small helpers ----------------
__device__ __forceinline__ float tf32r(float x) {
    uint32_t u;
    asm("cvt.rna.tf32.f32 %0, %1;" : "=r"(u) : "f"(x));
    return __uint_as_float(u);
}

__device__ __forceinline__ void mma_tf32(float* c, const uint32_t* a, const uint32_t* b) {
    asm volatile(
        "mma.sync.aligned.m16n8k8.row.col.f32.tf32.tf32.f32 "
        "{%0,%1,%2,%3}, {%4,%5,%6,%7}, {%8,%9}, {%0,%1,%2,%3};"
        : "+f"(c[0]), "+f"(c[1]), "+f"(c[2]), "+f"(c[3])
        : "r"(a[0]), "r"(a[1]), "r"(a[2]), "r"(a[3]), "r"(b[0]), "r"(b[1]));
}

__device__ __forceinline__ void cpa16(float* dst, const float* src) {
    asm volatile("cp.async.cg.shared.global [%0], [%1], 16;"
                 :: "r"((uint32_t)__cvta_generic_to_shared(dst)), "l"(src));
}
__device__ __forceinline__ void cpa_commit() {
    asm volatile("cp.async.commit_group;" ::: "memory");
}
__device__ __forceinline__ void cpa_wait1() {
    asm volatile("cp.async.wait_group 1;" ::: "memory");
}
__device__ __forceinline__ void cpa_wait0() {
    asm volatile("cp.async.wait_group 0;" ::: "memory");
}

// ---------------- tf32 rounding copies ----------------
__global__ __launch_bounds__(256) void round_copy(const float* __restrict__ src,
                                                  float* __restrict__ dst, int n4) {
    int i = blockIdx.x * 256 + threadIdx.x;
    if (i >= n4) return;
    float4 v = ((const float4*)src)[i];
    v.x = tf32r(v.x); v.y = tf32r(v.y); v.z = tf32r(v.z); v.w = tf32r(v.w);
    ((float4*)dst)[i] = v;
}

struct RC8 { const float* src[8]; float* dst; int n4; };
__global__ __launch_bounds__(256) void round_copy8(RC8 p) {
    int i = blockIdx.x * 256 + threadIdx.x;
    if (i >= p.n4) return;
    float4 v = ((const float4*)p.src[blockIdx.y])[i];
    v.x = tf32r(v.x); v.y = tf32r(v.y); v.z = tf32r(v.z); v.w = tf32r(v.w);
    ((float4*)(p.dst + (size_t)blockIdx.y * p.n4 * 4))[i] = v;
}

// ---------------- core: 128 x BN tile, K-chunk 32, 3-stage cp.async ring ----------------
template <int BN, bool CVTA>
__device__ __forceinline__ void gemm_core(const float* __restrict__ Ab, long long lda,
                                          const float* __restrict__ Bb, long long ldb,
                                          int K, float* sm, int tid, int lane,
                                          int warp_m, int warp_n,
                                          float (&acc)[2][BN / 16][4]) {
    constexpr int ST = 36;
    constexpr int SLOT = (128 + BN) * ST;
    constexpr int NT = BN / 16;
    constexpr int BLD = BN / 32;

    float* slot0 = sm;
    float* slot1 = sm + SLOT;
    float* slot2 = sm + 2 * SLOT;

    const int nc = K >> 5;
    float4 rA[4];

    auto slotp = [&](int c) -> float* {
        int s = c % 3;
        return s == 0 ? slot0 : (s == 1 ? slot1 : slot2);
    };
    auto issue = [&](int c) {
        float* Ad = slotp(c);
        float* Bd = Ad + 128 * ST;
        int k0 = c << 5;
        if (!CVTA) {
#pragma unroll
            for (int j = 0; j < 4; j++) {
                int i = tid + j * 256;
                int r = i >> 3, c4 = i & 7;
                cpa16(Ad + r * ST + c4 * 4, Ab + (size_t)r * lda + k0 + c4 * 4);
            }
        }
#pragma unroll
        for (int j = 0; j < BLD; j++) {
            int i = tid + j * 256;
            int r = i >> 3, c4 = i & 7;
            cpa16(Bd + r * ST + c4 * 4, Bb + (size_t)r * ldb + k0 + c4 * 4);
        }
    };
    auto fetchA = [&](int c) {
        int k0 = c << 5;
#pragma unroll
        for (int j = 0; j < 4; j++) {
            int i = tid + j * 256;
            int r = i >> 3, c4 = i & 7;
            rA[j] = *(const float4*)(Ab + (size_t)r * lda + k0 + c4 * 4);
        }
    };
    auto stashA = [&](int c) {
        float* Ad = slotp(c);
#pragma unroll
        for (int j = 0; j < 4; j++) {
            int i = tid + j * 256;
            int r = i >> 3, c4 = i & 7;
            float* d = Ad + r * ST + c4 * 4;
            d[0] = tf32r(rA[j].x); d[1] = tf32r(rA[j].y);
            d[2] = tf32r(rA[j].z); d[3] = tf32r(rA[j].w);
        }
    };

    issue(0);
    cpa_commit();
    issue(1);
    cpa_commit();
    if (CVTA) {
        fetchA(0); stashA(0);
        fetchA(1); stashA(1);
    }
    cpa_wait1();
    __syncthreads();

    for (int c = 0; c < nc; c++) {
        bool more2 = (c + 2 < nc);
        if (more2) issue(c + 2);
        cpa_commit();
        if (CVTA && more2) fetchA(c + 2);

        float* Ac = slotp(c);
        float* Bc = Ac + 128 * ST;
#pragma unroll
        for (int ks = 0; ks < 4; ks++) {
            int kb = ks * 8 + (lane & 3);
            uint32_t af[2][4];
            int ar = warp_m * 32 + (lane >> 2);
#pragma unroll
            for (int mt = 0; mt < 2; mt++) {
                const float* ap = Ac + (ar + mt * 16) * ST + kb;
                af[mt][0] = __float_as_uint(ap[0]);
                af[mt][1] = __float_as_uint(ap[8 * ST]);
                af[mt][2] = __float_as_uint(ap[4]);
                af[mt][3] = __float_as_uint(ap[8 * ST + 4]);
            }
            uint32_t bf[NT][2];
            int br = warp_n * (NT * 8) + (lane >> 2);
#pragma unroll
            for (int nt = 0; nt < NT; nt++) {
                const float* bp = Bc + (br + nt * 8) * ST + kb;
                bf[nt][0] = __float_as_uint(bp[0]);
                bf[nt][1] = __float_as_uint(bp[4]);
            }
#pragma unroll
            for (int mt = 0; mt < 2; mt++)
#pragma unroll
                for (int nt = 0; nt < NT; nt++)
                    mma_tf32(acc[mt][nt], af[mt], bf[nt]);
        }

        if (CVTA && more2) stashA(c + 2);
        cpa_wait1();
        __syncthreads();
    }
    cpa_wait0();
}

struct GP {
    const float* A; long long lda, aB, aH;
    const float* B; long long ldb, bB, bH;
    float* C;       long long ldc, cB, cH;
    const float* bias;
    int K, relu;
};

template <int BN, bool CVTA, bool RO>
__global__ __launch_bounds__(256, 2) void gemm_std(GP p) {
    extern __shared__ float sm[];
    constexpr int NT = BN / 16;
    int tid = threadIdx.x, lane = tid & 31, wid = tid >> 5;
    int warp_m = wid & 3, warp_n = wid >> 2;
    int b = blockIdx.z / NH, h = blockIdx.z % NH;

    const float* Ab = p.A + (size_t)b * p.aB + (size_t)h * p.aH +
                      (size_t)(blockIdx.y * 128) * p.lda;
    const float* Bb = p.B + (size_t)b * p.bB + (size_t)h * p.bH +
                      (size_t)(blockIdx.x * BN) * p.ldb;

    float acc[2][NT][4];
#pragma unroll
    for (int mt = 0; mt < 2; mt++)
#pragma unroll
        for (int nt = 0; nt < NT; nt++)
#pragma unroll
            for (int i = 0; i < 4; i++) acc[mt][nt][i] = 0.f;

    gemm_core<BN, CVTA>(Ab, p.lda, Bb, p.ldb, p.K, sm, tid, lane, warp_m, warp_n, acc);

    float* Cb = p.C + (size_t)b * p.cB + (size_t)h * p.cH;
    int mbase = blockIdx.y * 128 + warp_m * 32 + (lane >> 2);
    int nbase = blockIdx.x * BN + warp_n * (NT * 8) + (lane & 3) * 2;

#pragma unroll
    for (int mt = 0; mt < 2; mt++) {
#pragma unroll
        for (int nt = 0; nt < NT; nt++) {
            int n = nbase + nt * 8;
#pragma unroll
            for (int hf = 0; hf < 2; hf++) {
                int m = mbase + mt * 16 + hf * 8;
                float v0 = acc[mt][nt][hf * 2];
                float v1 = acc[mt][nt][hf * 2 + 1];
                if (p.bias) { v0 += p.bias[n]; v1 += p.bias[n + 1]; }
                if (p.relu) { v0 = fmaxf(v0, 0.f); v1 = fmaxf(v1, 0.f); }
                if (RO) { v0 = tf32r(v0); v1 = tf32r(v1); }
                float2 o = {v0, v1};
                *(float2*)(Cb + (size_t)m * p.ldc + n) = o;
            }
        }
    }
}

// ---------------- fused QKV projection (128x64 tiles; better wave fill) ----------------
struct QKVP {
    const float* A[3];
    const float* W[3];
    const float* bias[3];
    float* C[3];
};

__global__ __launch_bounds__(256, 2) void gemm_qkv(QKVP p) {
    extern __shared__ float sm[];
    constexpr int BN = 64, NT = 4;
    int tid = threadIdx.x, lane = tid & 31, wid = tid >> 5;
    int warp_m = wid & 3, warp_n = wid >> 2;
    int sel = blockIdx.x >> 3;       // 0..2
    int nblk = blockIdx.x & 7;       // 8 n-blocks of 64

    const float* Ab = p.A[sel] + (size_t)(blockIdx.y * 128) * DIM;
    const float* Bb = p.W[sel] + (size_t)(nblk * BN) * DIM;

    float acc[2][NT][4];
#pragma unroll
    for (int mt = 0; mt < 2; mt++)
#pragma unroll
        for (int nt = 0; nt < NT; nt++)
#pragma unroll
            for (int i = 0; i < 4; i++) acc[mt][nt][i] = 0.f;

    gemm_core<BN, false>(Ab, DIM, Bb, DIM, DIM, sm, tid, lane, warp_m, warp_n, acc);

    const float* bias = p.bias[sel];
    float* Cb = p.C[sel];
    int mbase = blockIdx.y * 128 + warp_m * 32 + (lane >> 2);
    int nbase = nblk * BN + warp_n * (NT * 8) + (lane & 3) * 2;

#pragma unroll
    for (int mt = 0; mt < 2; mt++) {
#pragma unroll
        for (int nt = 0; nt < NT; nt++) {
            int n = nbase + nt * 8;
#pragma unroll
            for (int hf = 0; hf < 2; hf++) {
                int m = mbase + mt * 16 + hf * 8;
                float v0 = tf32r(acc[mt][nt][hf * 2] + bias[n]);
                float v1 = tf32r(acc[mt][nt][hf * 2 + 1] + bias[n + 1]);
                if (sel < 2) {
                    float2 o = {v0, v1};
                    *(float2*)(Cb + (size_t)m * DIM + n) = o;
                } else {
                    Cb[(size_t)n * (BB * LDQ) + m] = v0;
                    Cb[(size_t)(n + 1) * (BB * LDQ) + m] = v1;
                }
            }
        }
    }
}

// ---------------- CA K/V projection (side stream) ----------------
struct KVP {
    const float* A;
    const float* W[2];
    const float* bias[2];
    float* C[2];
};

__global__ __launch_bounds__(256, 2) void gemm_kv(KVP p) {
    extern __shared__ float sm[];
    constexpr int BN = 128, NT = 8;
    int tid = threadIdx.x, lane = tid & 31, wid = tid >> 5;
    int warp_m = wid & 3, warp_n = wid >> 2;
    int sel = blockIdx.x >> 2;
    int nblk = blockIdx.x & 3;

    const float* Ab = p.A + (size_t)(blockIdx.y * 128) * DIM;
    const float* Bb = p.W[sel] + (size_t)(nblk * BN) * DIM;

    float acc[2][NT][4];
#pragma unroll
    for (int mt = 0; mt < 2; mt++)
#pragma unroll
        for (int nt = 0; nt < NT; nt++)
#pragma unroll
            for (int i = 0; i < 4; i++) acc[mt][nt][i] = 0.f;

    gemm_core<BN, false>(Ab, DIM, Bb, DIM, DIM, sm, tid, lane, warp_m, warp_n, acc);

    const float* bias = p.bias[sel];
    float* Cb = p.C[sel];
    int mbase = blockIdx.y * 128 + warp_m * 32 + (lane >> 2);
    int nbase = nblk * BN + warp_n * (NT * 8) + (lane & 3) * 2;

#pragma unroll
    for (int mt = 0; mt < 2; mt++) {
#pragma unroll
        for (int nt = 0; nt < NT; nt++) {
            int n = nbase + nt * 8;
#pragma unroll
            for (int hf = 0; hf < 2; hf++) {
                int m = mbase + mt * 16 + hf * 8;
                float v0 = tf32r(acc[mt][nt][hf * 2] + bias[n]);
                float v1 = tf32r(acc[mt][nt][hf * 2 + 1] + bias[n + 1]);
                if (sel == 0) {
                    float2 o = {v0, v1};
                    *(float2*)(Cb + (size_t)m * DIM + n) = o;
                } else {
                    Cb[(size_t)n * (BB * LDQ) + m] = v0;
                    Cb[(size_t)(n + 1) * (BB * LDQ) + m] = v1;
                }
            }
        }
    }
}

// ---------------- fused scores + mask + softmax (K streamed in 2 chunks) ----------------
#define STQ 68
#define SS_Q_FLOATS (32 * STQ)
#define SS_K_FLOATS (256 * STQ)
#define SS_SMEM_BYTES ((SS_Q_FLOATS + SS_K_FLOATS) * 4 + 512 * 4 + 32 * 8 * 4 + 32 * 4)

struct SSP {
    const float* Q;
    const float* K;
    const int* tok;
    float* S;
    int causal;
};

__global__ __launch_bounds__(256, 2) void scores_softmax(SSP p) {
    extern __shared__ float sm[];
    float* sQ = sm;
    float* sK = sm + SS_Q_FLOATS;
    int* stok = (int*)(sm + SS_Q_FLOATS + SS_K_FLOATS);
    float* red = (float*)(stok + 512);
    float* rowstat = red + 32 * 8;

    int tid = threadIdx.x, lane = tid & 31, w = tid >> 5;
    int bh = blockIdx.y;
    int b = bh / NH, h = bh % NH;
    int q0 = blockIdx.x * 32;

    const float* Qb = p.Q + (size_t)b * LDQ * DIM + (size_t)h * 64 + (size_t)q0 * DIM;
    const float* Kb = p.K + (size_t)b * LDQ * DIM + (size_t)h * 64;
    const int* tokb = p.tok + b * 512;

#pragma unroll
    for (int j = 0; j < 2; j++) {
        int i = tid + j * 256;
        int r = i >> 4, c4 = i & 15;
        cpa16(sQ + r * STQ + c4 * 4, Qb + (size_t)r * DIM + c4 * 4);
    }
#pragma unroll
    for (int j = 0; j < 16; j++) {
        int i = tid + j * 256;
        int r = i >> 4, c4 = i & 15;
        cpa16(sK + r * STQ + c4 * 4, Kb + (size_t)r * DIM + c4 * 4);
    }
    cpa_commit();
    stok[tid] = tokb[tid];
    stok[tid + 256] = tokb[tid + 256];
    cpa_wait0();
    __syncthreads();

    float acc[2][8][4];
#pragma unroll
    for (int mt = 0; mt < 2; mt++)
#pragma unroll
        for (int nt = 0; nt < 8; nt++)
#pragma unroll
            for (int i = 0; i < 4; i++) acc[mt][nt][i] = 0.f;

    for (int c = 0; c < 2; c++) {
#pragma unroll
        for (int ks = 0; ks < 8; ks++) {
            int kb = ks * 8 + (lane & 3);
            uint32_t af[2][4];
            int ar = lane >> 2;
#pragma unroll
            for (int mt = 0; mt < 2; mt++) {
                const float* ap = sQ + (ar + mt * 16) * STQ + kb;
                af[mt][0] = __float_as_uint(ap[0]);
                af[mt][1] = __float_as_uint(ap[8 * STQ]);
                af[mt][2] = __float_as_uint(ap[4]);
                af[mt][3] = __float_as_uint(ap[8 * STQ + 4]);
            }
            uint32_t bf[4][2];
            int br = w * 32 + (lane >> 2);
#pragma unroll
            for (int j = 0; j < 4; j++) {
                const float* bp = sK + (br + j * 8) * STQ + kb;
                bf[j][0] = __float_as_uint(bp[0]);
                bf[j][1] = __float_as_uint(bp[4]);
            }
#pragma unroll
            for (int mt = 0; mt < 2; mt++)
#pragma unroll
                for (int j = 0; j < 4; j++)
                    mma_tf32(acc[mt][c * 4 + j], af[mt], bf[j]);
        }
        if (c == 0) {
            __syncthreads();
#pragma unroll
            for (int j = 0; j < 16; j++) {
                int i = tid + j * 256;
                int r = i >> 4, c4 = i & 15;
                cpa16(sK + r * STQ + c4 * 4, Kb + (size_t)(256 + r) * DIM + c4 * 4);
            }
            cpa_commit();
            cpa_wait0();
            __syncthreads();
        }
    }

    float lmax[2][2] = {{-1e30f, -1e30f}, {-1e30f, -1e30f}};
#pragma unroll
    for (int mt = 0; mt < 2; mt++)
#pragma unroll
        for (int nt = 0; nt < 8; nt++)
#pragma unroll
            for (int j = 0; j < 4; j++) {
                int hf = j >> 1;
                int col = (nt >> 2) * 256 + w * 32 + (nt & 3) * 8 + (lane & 3) * 2 + (j & 1);
                int row = mt * 16 + (lane >> 2) + hf * 8;
                float v = acc[mt][nt][j] * 0.125f;
                bool msk = (stok[col] == 0) || (p.causal && col > q0 + row);
                v = msk ? -1e9f : v;
                acc[mt][nt][j] = v;
                lmax[mt][hf] = fmaxf(lmax[mt][hf], v);
            }
#pragma unroll
    for (int mt = 0; mt < 2; mt++)
#pragma unroll
        for (int hf = 0; hf < 2; hf++) {
            float v = lmax[mt][hf];
            v = fmaxf(v, __shfl_xor_sync(0xffffffffu, v, 1));
            v = fmaxf(v, __shfl_xor_sync(0xffffffffu, v, 2));
            lmax[mt][hf] = v;
        }
    if ((lane & 3) == 0) {
        int r0 = lane >> 2;
        red[(r0) * 8 + w] = lmax[0][0];
        red[(r0 + 8) * 8 + w] = lmax[0][1];
        red[(r0 + 16) * 8 + w] = lmax[1][0];
        red[(r0 + 24) * 8 + w] = lmax[1][1];
    }
    __syncthreads();
    if (tid < 32) {
        float m = red[tid * 8];
#pragma unroll
        for (int i = 1; i < 8; i++) m = fmaxf(m, red[tid * 8 + i]);
        rowstat[tid] = m;
    }
    __syncthreads();

    float rmax[2][2];
#pragma unroll
    for (int mt = 0; mt < 2; mt++)
#pragma unroll
        for (int hf = 0; hf < 2; hf++)
            rmax[mt][hf] = rowstat[mt * 16 + (lane >> 2) + hf * 8];
    __syncthreads();

    float lsum[2][2] = {{0.f, 0.f}, {0.f, 0.f}};
#pragma unroll
    for (int mt = 0; mt < 2; mt++)
#pragma unroll
        for (int nt = 0; nt < 8; nt++)
#pragma unroll
            for (int j = 0; j < 4; j++) {
                int hf = j >> 1;
                float e = expf(acc[mt][nt][j] - rmax[mt][hf]);
                acc[mt][nt][j] = e;
                lsum[mt][hf] += e;
            }
#pragma unroll
    for (int mt = 0; mt < 2; mt++)
#pragma unroll
        for (int hf = 0; hf < 2; hf++) {
            float v = lsum[mt][hf];
            v += __shfl_xor_sync(0xffffffffu, v, 1);
            v += __shfl_xor_sync(0xffffffffu, v, 2);
            lsum[mt][hf] = v;
        }
    if ((lane & 3) == 0) {
        int r0 = lane >> 2;
        red[(r0) * 8 + w] = lsum[0][0];
        red[(r0 + 8) * 8 + w] = lsum[0][1];
        red[(r0 + 16) * 8 + w] = lsum[1][0];
        red[(r0 + 24) * 8 + w] = lsum[1][1];
    }
    __syncthreads();
    if (tid < 32) {
        float s = 0.f;
#pragma unroll
        for (int i = 0; i < 8; i++) s += red[tid * 8 + i];
        rowstat[tid] = 1.f / s;
    }
    __syncthreads();

    float rinv[2][2];
#pragma unroll
    for (int mt = 0; mt < 2; mt++)
#pragma unroll
        for (int hf = 0; hf < 2; hf++)
            rinv[mt][hf] = rowstat[mt * 16 + (lane >> 2) + hf * 8];

    float* Sb = p.S + (size_t)bh * LDQ * 512;
#pragma unroll
    for (int mt = 0; mt < 2; mt++)
#pragma unroll
        for (int nt = 0; nt < 8; nt++)
#pragma unroll
            for (int hf = 0; hf < 2; hf++) {
                int row = q0 + mt * 16 + (lane >> 2) + hf * 8;
                int col = (nt >> 2) * 256 + w * 32 + (nt & 3) * 8 + (lane & 3) * 2;
                float2 o = {acc[mt][nt][hf * 2] * rinv[mt][hf],
                            acc[mt][nt][hf * 2 + 1] * rinv[mt][hf]};
                *(float2*)(Sb + (size_t)row * 512 + col) = o;
            }
}

// ---------------- reductions ----------------
__device__ __forceinline__ float blockReduceSum256(float v, float* red) {
    int lane = threadIdx.x & 31, wid = threadIdx.x >> 5;
#pragma unroll
    for (int o = 16; o > 0; o >>= 1) v += __shfl_xor_sync(0xffffffffu, v, o);
    if (lane == 0) red[wid] = v;
    __syncthreads();
    float r = 0.f;
    if (threadIdx.x < 8) r = red[threadIdx.x];
    if (wid == 0) {
#pragma unroll
        for (int o = 4; o > 0; o >>= 1) r += __shfl_xor_sync(0xffu, r, o);
        if (lane == 0) red[0] = r;
    }
    __syncthreads();
    float out = red[0];
    __syncthreads();
    return out;
}

// ---------------- embedding + sinusoidal position ----------------
__global__ __launch_bounds__(256) void embed_kernel(const int* __restrict__ dec,
                                                    const float* __restrict__ emb,
                                                    float* __restrict__ x,
                                                    float* __restrict__ xr) {
    int idx = blockIdx.x * 256 + threadIdx.x;
    if (idx >= BB * LDQ * DIM) return;
    int d = idx & (DIM - 1);
    int bl = idx / DIM;
    int l = bl & (LDQ - 1);
    int tok = dec[bl];
    double pos = (double)(l + 1);
    int jhalf = d >> 1;
    double denom = pow(10000.0, (double)(2 * jhalf) / (double)DIM);
    double a = pos / denom;
    float pe = ((d & 1) == 0) ? (float)sin(a) : (float)cos(a);
    float v = emb[(size_t)tok * DIM + d] + pe;
    x[idx] = v;
    xr[idx] = tf32r(v);
}

// ---------------- residual add + layernorm (dual write) ----------------
__global__ __launch_bounds__(256) void add_ln(const float* __restrict__ A,
                                              const float* __restrict__ R,
                                              const float* __restrict__ g,
                                              const float* __restrict__ be,
                                              float* __restrict__ out,
                                              float* __restrict__ outr) {
    int row = blockIdx.x;
    int t = threadIdx.x;
    __shared__ float red[32];
    const float* a = A + (size_t)row * DIM;
    const float* r = R + (size_t)row * DIM;
    float x0 = a[t] + r[t];
    float x1 = a[t + 256] + r[t + 256];
    float s = blockReduceSum256(x0 + x1, red);
    float mean = s * (1.f / 512.f);
    float d0 = x0 - mean, d1 = x1 - mean;
    float s2 = blockReduceSum256(d0 * d0 + d1 * d1, red);
    float inv = rsqrtf(s2 * (1.f / 512.f) + 1e-5f);
    float o0 = d0 * inv * g[t] + be[t];
    float o1 = d1 * inv * g[t + 256] + be[t + 256];
    out[(size_t)row * DIM + t] = o0;
    out[(size_t)row * DIM + t + 256] = o1;
    outr[(size_t)row * DIM + t] = tf32r(o0);
    outr[(size_t)row * DIM + t + 256] = tf32r(o1);
}

// ---------------- host orchestration ----------------
#define SMEM128 (3 * (128 + 128) * 36 * 4)
#define SMEM64  (3 * (128 + 64) * 36 * 4)

struct Res {
    cudaStream_t s2;
    cudaEvent_t e1, eL[NLAY];
    Res() {
        cudaStreamCreateWithFlags(&s2, cudaStreamNonBlocking);
        cudaEventCreateWithFlags(&e1, cudaEventDisableTiming);
        for (int l = 0; l < NLAY; l++)
            cudaEventCreateWithFlags(&eL[l], cudaEventDisableTiming);
    }
};

extern "C" void kernel_launch(void* const* d_in, const int* in_sizes, int n_in,
                              void* d_out, int out_size) {
    static Res res;

    const int* dec = (const int*)d_in[0];
    const int* enc = (const int*)d_in[1];
    const float* enc_out = (const float*)d_in[2];
    const float* emb = (const float*)d_in[3];

    bool dict_order = (in_sizes[5] == NLAY * DIM * DIM);
    int iwq[2], iwk[2], iwv[2], iwo[2], ibq[2], ibk[2], ibv[2], ibo[2], ig[2], ib[2];
    for (int p = 0; p < 2; p++) {
        int base = 4 + p * 10;
        if (dict_order) {
            iwq[p] = base + 0; iwk[p] = base + 1; iwv[p] = base + 2; iwo[p] = base + 3;
            ibq[p] = base + 4; ibk[p] = base + 5; ibv[p] = base + 6; ibo[p] = base + 7;
            ig[p] = base + 8; ib[p] = base + 9;
        } else {
            iwq[p] = base + 0; ibq[p] = base + 1; iwk[p] = base + 2; ibk[p] = base + 3;
            iwv[p] = base + 4; ibv[p] = base + 5; iwo[p] = base + 6; ibo[p] = base + 7;
            ig[p] = base + 8; ib[p] = base + 9;
        }
    }
    const float* ffn_b1 = (const float*)d_in[25];
    const float* ffn_b2 = (const float*)d_in[27];
    const float* ffn_g = (const float*)d_in[28];
    const float* ffn_bb = (const float*)d_in[29];

    float *x, *xr, *encr, *q, *k, *vt, *ctxp, *proj, *ffh, *wr, *w1r, *w2r, *kca, *vtca;
    cudaGetSymbolAddress((void**)&x, g_x);
    cudaGetSymbolAddress((void**)&xr, g_xr);
    cudaGetSymbolAddress((void**)&encr, g_encr);
    cudaGetSymbolAddress((void**)&q, g_q);
    cudaGetSymbolAddress((void**)&k, g_k);
    cudaGetSymbolAddress((void**)&vt, g_vt);
    cudaGetSymbolAddress((void**)&ctxp, g_ctx);
    cudaGetSymbolAddress((void**)&proj, g_proj);
    cudaGetSymbolAddress((void**)&ffh, g_ffh);
    cudaGetSymbolAddress((void**)&wr, g_wr);
    cudaGetSymbolAddress((void**)&w1r, g_w1r);
    cudaGetSymbolAddress((void**)&w2r, g_w2r);
    cudaGetSymbolAddress((void**)&kca, g_kca);
    cudaGetSymbolAddress((void**)&vtca, g_vtca);

    cudaFuncSetAttribute(gemm_qkv, cudaFuncAttributeMaxDynamicSharedMemorySize, SMEM64);
    cudaFuncSetAttribute(gemm_kv, cudaFuncAttributeMaxDynamicSharedMemorySize, SMEM128);
    cudaFuncSetAttribute((const void*)gemm_std<64, false, true>,
                         cudaFuncAttributeMaxDynamicSharedMemorySize, SMEM64);
    cudaFuncSetAttribute((const void*)gemm_std<64, true, true>,
                         cudaFuncAttributeMaxDynamicSharedMemorySize, SMEM64);
    cudaFuncSetAttribute((const void*)gemm_std<64, false, false>,
                         cudaFuncAttributeMaxDynamicSharedMemorySize, SMEM64);
    cudaFuncSetAttribute(scores_softmax, cudaFuncAttributeMaxDynamicSharedMemorySize, SS_SMEM_BYTES);

    float* out = (float*)d_out;
    const size_t XSZ = (size_t)BB * LDQ * DIM;
    const size_t AW = (size_t)BB * NH * LDQ * LDQ;
    float* sa_base = out + XSZ;
    float* ca_base = out + XSZ + (size_t)NLAY * AW;

    const int M = BB * LDQ;
    const long long LL = (long long)LDQ * LDQ;
    const int WSZ = NLAY * DIM * DIM;

    // main: round weights first
    {
        RC8 rc;
        for (int p = 0; p < 2; p++) {
            int idxs[4] = {iwq[p], iwk[p], iwv[p], iwo[p]};
            for (int j = 0; j < 4; j++) rc.src[p * 4 + j] = (const float*)d_in[idxs[j]];
        }
        rc.dst = wr;
        rc.n4 = WSZ / 4;
        round_copy8<<<dim3((rc.n4 + 255) / 256, 8), 256>>>(rc);
    }
    cudaEventRecord(res.e1, 0);

    // s2: encr round + all 6 CA K/V projections
    cudaStreamWaitEvent(res.s2, res.e1, 0);
    {
        int n4 = (BB * LDQ * DIM) / 4;
        round_copy<<<(n4 + 255) / 256, 256, 0, res.s2>>>(enc_out, encr, n4);
        for (int l = 0; l < NLAY; l++) {
            size_t wofs = (size_t)l * DIM * DIM;
            size_t bofs = (size_t)l * DIM;
            KVP kp;
            kp.A = encr;
            kp.W[0] = wr + (size_t)(1 * 4 + 1) * WSZ + wofs;
            kp.W[1] = wr + (size_t)(1 * 4 + 2) * WSZ + wofs;
            kp.bias[0] = (const float*)d_in[ibk[1]] + bofs;
            kp.bias[1] = (const float*)d_in[ibv[1]] + bofs;
            kp.C[0] = kca + (size_t)l * XSZ;
            kp.C[1] = vtca + (size_t)l * XSZ;
            gemm_kv<<<dim3(8, 32), 256, SMEM128, res.s2>>>(kp);
            cudaEventRecord(res.eL[l], res.s2);
        }
    }

    // main: remaining pre-rounds + embed
    {
        int f4 = (NLAY * FFD * DIM) / 4;
        round_copy<<<(f4 + 255) / 256, 256>>>((const float*)d_in[24], w1r, f4);
        round_copy<<<(f4 + 255) / 256, 256>>>((const float*)d_in[26], w2r, f4);
    }
    embed_kernel<<<(BB * LDQ * DIM + 255) / 256, 256>>>(dec, emb, x, xr);

    for (int l = 0; l < NLAY; l++) {
        size_t wofs = (size_t)l * DIM * DIM;
        size_t bofs = (size_t)l * DIM;

        for (int p = 0; p < 2; p++) {
            const float* wq = wr + (size_t)(p * 4 + 0) * WSZ + wofs;
            const float* wk = wr + (size_t)(p * 4 + 1) * WSZ + wofs;
            const float* wv = wr + (size_t)(p * 4 + 2) * WSZ + wofs;
            const float* wo = wr + (size_t)(p * 4 + 3) * WSZ + wofs;
            const float* bq = (const float*)d_in[ibq[p]] + bofs;
            const float* bk = (const float*)d_in[ibk[p]] + bofs;
            const float* bv = (const float*)d_in[ibv[p]] + bofs;
            const float* bo = (const float*)d_in[ibo[p]] + bofs;
            const float* gg = (const float*)d_in[ig[p]] + bofs;
            const float* bt = (const float*)d_in[ib[p]] + bofs;

            const int* tok = (p == 0) ? dec : enc;
            int causal = (p == 0) ? 1 : 0;
            float* S = ((p == 0) ? sa_base : ca_base) + (size_t)l * AW;

            const float* kuse;
            const float* vtuse;
            if (p == 0) {
                QKVP qp;
                qp.A[0] = xr; qp.A[1] = xr; qp.A[2] = xr;
                qp.W[0] = wq; qp.W[1] = wk; qp.W[2] = wv;
                qp.bias[0] = bq; qp.bias[1] = bk; qp.bias[2] = bv;
                qp.C[0] = q;  qp.C[1] = k;  qp.C[2] = vt;
                gemm_qkv<<<dim3(24, 32), 256, SMEM64>>>(qp);
                kuse = k; vtuse = vt;
            } else {
                GP gq = GP{xr, DIM, 0, 0, wq, DIM, 0, 0, q, DIM, 0, 0, bq, DIM, 0};
                gemm_std<64, false, true><<<dim3(8, 32, 1), 256, SMEM64>>>(gq);
                cudaStreamWaitEvent(0, res.eL[l], 0);
                kuse = kca + (size_t)l * XSZ;
                vtuse = vtca + (size_t)l * XSZ;
            }

            SSP sp{q, kuse, tok, S, causal};
            scores_softmax<<<dim3(16, BB * NH), 256, SS_SMEM_BYTES>>>(sp);

            GP gp;
            gp = GP{S, LDQ, NH * LL, LL, vtuse, M, LDQ, 64LL * M, ctxp, DIM, LL, 64,
                    nullptr, 512, 0};
            gemm_std<64, true, true><<<dim3(1, 4, BB * NH), 256, SMEM64>>>(gp);
            gp = GP{ctxp, DIM, 0, 0, wo, DIM, 0, 0, proj, DIM, 0, 0, bo, DIM, 0};
            gemm_std<64, false, false><<<dim3(8, 32, 1), 256, SMEM64>>>(gp);
            add_ln<<<M, 256>>>(proj, x, gg, bt, x, xr);
        }

        // FFN
        GP gp;
        gp = GP{xr, DIM, 0, 0, w1r + (size_t)l * FFD * DIM, DIM, 0, 0,
                ffh, FFD, 0, 0, ffn_b1 + (size_t)l * FFD, DIM, 1};
        gemm_std<64, false, true><<<dim3(32, 32, 1), 256, SMEM64>>>(gp);
        gp = GP{ffh, FFD, 0, 0, w2r + (size_t)l * DIM * FFD, FFD, 0, 0,
                proj, DIM, 0, 0, ffn_b2 + bofs, FFD, 0};
        gemm_std<64, false, false><<<dim3(8, 32, 1), 256, SMEM64>>>(gp);
        float* lnout = (l == NLAY - 1) ? out : x;
        add_ln<<<M, 256>>>(proj, x, ffn_g + bofs, ffn_bb + bofs, lnout, xr);
    }
}

// round 15
// speedup vs baseline: 1.0326x; 1.0326x over previous
#include <cuda_runtime.h>
#include <cstdint>
#include <math.h>

#define BB 8
#define LDQ 512
#define DIM 512
#define NH 8
#define FFD 2048
#define NLAY 6

// ---------------- scratch (static device globals; no allocation) ----------------
__device__ float g_x[BB * LDQ * DIM];
__device__ float g_xr[BB * LDQ * DIM];
__device__ float g_encr[BB * LDQ * DIM];
__device__ float g_q[BB * LDQ * DIM];
__device__ float g_k[BB * LDQ * DIM];
__device__ float g_vt[DIM * BB * LDQ];
__device__ float g_ctx[BB * LDQ * DIM];
__device__ float g_proj[BB * LDQ * DIM];
__device__ float g_ffh[BB * LDQ * FFD];
__device__ float g_wr[8 * NLAY * DIM * DIM];
__device__ float g_w1r[NLAY * FFD * DIM];
__device__ float g_w2r[NLAY * DIM * FFD];
__device__ float g_kca[NLAY * BB * LDQ * DIM];
__device__ float g_vtca[NLAY * DIM * BB * LDQ];

// ---------------- small helpers ----------------
__device__ __forceinline__ float tf32r(float x) {
    uint32_t u;
    asm("cvt.rna.tf32.f32 %0, %1;" : "=r"(u) : "f"(x));
    return __uint_as_float(u);
}

__device__ __forceinline__ void mma_tf32(float* c, const uint32_t* a, const uint32_t* b) {
    asm volatile(
        "mma.sync.aligned.m16n8k8.row.col.f32.tf32.tf32.f32 "
        "{%0,%1,%2,%3}, {%4,%5,%6,%7}, {%8,%9}, {%0,%1,%2,%3};"
        : "+f"(c[0]), "+f"(c[1]), "+f"(c[2]), "+f"(c[3])
        : "r"(a[0]), "r"(a[1]), "r"(a[2]), "r"(a[3]), "r"(b[0]), "r"(b[1]));
}

__device__ __forceinline__ void cpa16(float* dst, const float* src) {
    asm volatile("cp.async.cg.shared.global [%0], [%1], 16;"
                 :: "r"((uint32_t)__cvta_generic_to_shared(dst)), "l"(src));
}
__device__ __forceinline__ void cpa_commit() {
    asm volatile("cp.async.commit_group;" ::: "memory");
}
__device__ __forceinline__ void cpa_wait1() {
    asm volatile("cp.async.wait_group 1;" ::: "memory");
}
__device__ __forceinline__ void cpa_wait0() {
    asm volatile("cp.async.wait_group 0;" ::: "memory");
}

// ---------------- tf32 rounding copies ----------------
__global__ __launch_bounds__(256) void round_copy(const float* __restrict__ src,
                                                  float* __restrict__ dst, int n4) {
    int i = blockIdx.x * 256 + threadIdx.x;
    if (i >= n4) return;
    float4 v = ((const float4*)src)[i];
    v.x = tf32r(v.x); v.y = tf32r(v.y); v.z = tf32r(v.z); v.w = tf32r(v.w);
    ((float4*)dst)[i] = v;
}

struct RC8 { const float* src[8]; float* dst; int n4; };
__global__ __launch_bounds__(256) void round_copy8(RC8 p) {
    int i = blockIdx.x * 256 + threadIdx.x;
    if (i >= p.n4) return;
    float4 v = ((const float4*)p.src[blockIdx.y])[i];
    v.x = tf32r(v.x); v.y = tf32r(v.y); v.z = tf32r(v.z); v.w = tf32r(v.w);
    ((float4*)(p.dst + (size_t)blockIdx.y * p.n4 * 4))[i] = v;
}

// ---------------- core: 128 x BN tile, K-chunk 32, 3-stage cp.async ring ----------------
template <int BN, bool CVTA>
__device__ __forceinline__ void gemm_core(const float* __restrict__ Ab, long long lda,
                                          const float* __restrict__ Bb, long long ldb,
                                          int K, float* sm, int tid, int lane,
                                          int warp_m, int warp_n,
                                          float (&acc)[2][BN / 16][4]) {
    constexpr int ST = 36;
    constexpr int SLOT = (128 + BN) * ST;
    constexpr int NT = BN / 16;
    constexpr int BLD = BN / 32;

    float* slot0 = sm;
    float* slot1 = sm + SLOT;
    float* slot2 = sm + 2 * SLOT;

    const int nc = K >> 5;
    float4 rA[4];

    auto slotp = [&](int c) -> float* {
        int s = c % 3;
        return s == 0 ? slot0 : (s == 1 ? slot1 : slot2);
    };
    auto issue = [&](int c) {
        float* Ad = slotp(c);
        float* Bd = Ad + 128 * ST;
        int k0 = c << 5;
        if (!CVTA) {
#pragma unroll
            for (int j = 0; j < 4; j++) {
                int i = tid + j * 256;
                int r = i >> 3, c4 = i & 7;
                cpa16(Ad + r * ST + c4 * 4, Ab + (size_t)r * lda + k0 + c4 * 4);
            }
        }
#pragma unroll
        for (int j = 0; j < BLD; j++) {
            int i = tid + j * 256;
            int r = i >> 3, c4 = i & 7;
            cpa16(Bd + r * ST + c4 * 4, Bb + (size_t)r * ldb + k0 + c4 * 4);
        }
    };
    auto fetchA = [&](int c) {
        int k0 = c << 5;
#pragma unroll
        for (int j = 0; j < 4; j++) {
            int i = tid + j * 256;
            int r = i >> 3, c4 = i & 7;
            rA[j] = *(const float4*)(Ab + (size_t)r * lda + k0 + c4 * 4);
        }
    };
    auto stashA = [&](int c) {
        float* Ad = slotp(c);
#pragma unroll
        for (int j = 0; j < 4; j++) {
            int i = tid + j * 256;
            int r = i >> 3, c4 = i & 7;
            float* d = Ad + r * ST + c4 * 4;
            d[0] = tf32r(rA[j].x); d[1] = tf32r(rA[j].y);
            d[2] = tf32r(rA[j].z); d[3] = tf32r(rA[j].w);
        }
    };

    issue(0);
    cpa_commit();
    issue(1);
    cpa_commit();
    if (CVTA) {
        fetchA(0); stashA(0);
        fetchA(1); stashA(1);
    }
    cpa_wait1();
    __syncthreads();

    for (int c = 0; c < nc; c++) {
        bool more2 = (c + 2 < nc);
        if (more2) issue(c + 2);
        cpa_commit();
        if (CVTA && more2) fetchA(c + 2);

        float* Ac = slotp(c);
        float* Bc = Ac + 128 * ST;
#pragma unroll
        for (int ks = 0; ks < 4; ks++) {
            int kb = ks * 8 + (lane & 3);
            uint32_t af[2][4];
            int ar = warp_m * 32 + (lane >> 2);
#pragma unroll
            for (int mt = 0; mt < 2; mt++) {
                const float* ap = Ac + (ar + mt * 16) * ST + kb;
                af[mt][0] = __float_as_uint(ap[0]);
                af[mt][1] = __float_as_uint(ap[8 * ST]);
                af[mt][2] = __float_as_uint(ap[4]);
                af[mt][3] = __float_as_uint(ap[8 * ST + 4]);
            }
            uint32_t bf[NT][2];
            int br = warp_n * (NT * 8) + (lane >> 2);
#pragma unroll
            for (int nt = 0; nt < NT; nt++) {
                const float* bp = Bc + (br + nt * 8) * ST + kb;
                bf[nt][0] = __float_as_uint(bp[0]);
                bf[nt][1] = __float_as_uint(bp[4]);
            }
#pragma unroll
            for (int mt = 0; mt < 2; mt++)
#pragma unroll
                for (int nt = 0; nt < NT; nt++)
                    mma_tf32(acc[mt][nt], af[mt], bf[nt]);
        }

        if (CVTA && more2) stashA(c + 2);
        cpa_wait1();
        __syncthreads();
    }
    cpa_wait0();
}

struct GP {
    const float* A; long long lda, aB, aH;
    const float* B; long long ldb, bB, bH;
    float* C;       long long ldc, cB, cH;
    const float* bias;
    int K, relu;
};

template <int BN, bool CVTA, bool RO>
__global__ __launch_bounds__(256, 2) void gemm_std(GP p) {
    extern __shared__ float sm[];
    constexpr int NT = BN / 16;
    int tid = threadIdx.x, lane = tid & 31, wid = tid >> 5;
    int warp_m = wid & 3, warp_n = wid >> 2;
    int b = blockIdx.z / NH, h = blockIdx.z % NH;

    const float* Ab = p.A + (size_t)b * p.aB + (size_t)h * p.aH +
                      (size_t)(blockIdx.y * 128) * p.lda;
    const float* Bb = p.B + (size_t)b * p.bB + (size_t)h * p.bH +
                      (size_t)(blockIdx.x * BN) * p.ldb;

    float acc[2][NT][4];
#pragma unroll
    for (int mt = 0; mt < 2; mt++)
#pragma unroll
        for (int nt = 0; nt < NT; nt++)
#pragma unroll
            for (int i = 0; i < 4; i++) acc[mt][nt][i] = 0.f;

    gemm_core<BN, CVTA>(Ab, p.lda, Bb, p.ldb, p.K, sm, tid, lane, warp_m, warp_n, acc);

    float* Cb = p.C + (size_t)b * p.cB + (size_t)h * p.cH;
    int mbase = blockIdx.y * 128 + warp_m * 32 + (lane >> 2);
    int nbase = blockIdx.x * BN + warp_n * (NT * 8) + (lane & 3) * 2;

#pragma unroll
    for (int mt = 0; mt < 2; mt++) {
#pragma unroll
        for (int nt = 0; nt < NT; nt++) {
            int n = nbase + nt * 8;
#pragma unroll
            for (int hf = 0; hf < 2; hf++) {
                int m = mbase + mt * 16 + hf * 8;
                float v0 = acc[mt][nt][hf * 2];
                float v1 = acc[mt][nt][hf * 2 + 1];
                if (p.bias) { v0 += p.bias[n]; v1 += p.bias[n + 1]; }
                if (p.relu) { v0 = fmaxf(v0, 0.f); v1 = fmaxf(v1, 0.f); }
                if (RO) { v0 = tf32r(v0); v1 = tf32r(v1); }
                float2 o = {v0, v1};
                *(float2*)(Cb + (size_t)m * p.ldc + n) = o;
            }
        }
    }
}

// ---------------- fused QKV projection (128x128 tiles) ----------------
struct QKVP {
    const float* A[3];
    const float* W[3];
    const float* bias[3];
    float* C[3];
};

__global__ __launch_bounds__(256, 2) void gemm_qkv(QKVP p) {
    extern __shared__ float sm[];
    constexpr int BN = 128, NT = 8;
    int tid = threadIdx.x, lane = tid & 31, wid = tid >> 5;
    int warp_m = wid & 3, warp_n = wid >> 2;
    int sel = blockIdx.x >> 2;
    int nblk = blockIdx.x & 3;

    const float* Ab = p.A[sel] + (size_t)(blockIdx.y * 128) * DIM;
    const float* Bb = p.W[sel] + (size_t)(nblk * BN) * DIM;

    float acc[2][NT][4];
#pragma unroll
    for (int mt = 0; mt < 2; mt++)
#pragma unroll
        for (int nt = 0; nt < NT; nt++)
#pragma unroll
            for (int i = 0; i < 4; i++) acc[mt][nt][i] = 0.f;

    gemm_core<BN, false>(Ab, DIM, Bb, DIM, DIM, sm, tid, lane, warp_m, warp_n, acc);

    const float* bias = p.bias[sel];
    float* Cb = p.C[sel];
    int mbase = blockIdx.y * 128 + warp_m * 32 + (lane >> 2);
    int nbase = nblk * BN + warp_n * (NT * 8) + (lane & 3) * 2;

#pragma unroll
    for (int mt = 0; mt < 2; mt++) {
#pragma unroll
        for (int nt = 0; nt < NT; nt++) {
            int n = nbase + nt * 8;
#pragma unroll
            for (int hf = 0; hf < 2; hf++) {
                int m = mbase + mt * 16 + hf * 8;
                float v0 = tf32r(acc[mt][nt][hf * 2] + bias[n]);
                float v1 = tf32r(acc[mt][nt][hf * 2 + 1] + bias[n + 1]);
                if (sel < 2) {
                    float2 o = {v0, v1};
                    *(float2*)(Cb + (size_t)m * DIM + n) = o;
                } else {
                    Cb[(size_t)n * (BB * LDQ) + m] = v0;
                    Cb[(size_t)(n + 1) * (BB * LDQ) + m] = v1;
                }
            }
        }
    }
}

// ---------------- CA K/V projection (side stream) ----------------
struct KVP {
    const float* A;
    const float* W[2];
    const float* bias[2];
    float* C[2];
};

__global__ __launch_bounds__(256, 2) void gemm_kv(KVP p) {
    extern __shared__ float sm[];
    constexpr int BN = 128, NT = 8;
    int tid = threadIdx.x, lane = tid & 31, wid = tid >> 5;
    int warp_m = wid & 3, warp_n = wid >> 2;
    int sel = blockIdx.x >> 2;
    int nblk = blockIdx.x & 3;

    const float* Ab = p.A + (size_t)(blockIdx.y * 128) * DIM;
    const float* Bb = p.W[sel] + (size_t)(nblk * BN) * DIM;

    float acc[2][NT][4];
#pragma unroll
    for (int mt = 0; mt < 2; mt++)
#pragma unroll
        for (int nt = 0; nt < NT; nt++)
#pragma unroll
            for (int i = 0; i < 4; i++) acc[mt][nt][i] = 0.f;

    gemm_core<BN, false>(Ab, DIM, Bb, DIM, DIM, sm, tid, lane, warp_m, warp_n, acc);

    const float* bias = p.bias[sel];
    float* Cb = p.C[sel];
    int mbase = blockIdx.y * 128 + warp_m * 32 + (lane >> 2);
    int nbase = nblk * BN + warp_n * (NT * 8) + (lane & 3) * 2;

#pragma unroll
    for (int mt = 0; mt < 2; mt++) {
#pragma unroll
        for (int nt = 0; nt < NT; nt++) {
            int n = nbase + nt * 8;
#pragma unroll
            for (int hf = 0; hf < 2; hf++) {
                int m = mbase + mt * 16 + hf * 8;
                float v0 = tf32r(acc[mt][nt][hf * 2] + bias[n]);
                float v1 = tf32r(acc[mt][nt][hf * 2 + 1] + bias[n + 1]);
                if (sel == 0) {
                    float2 o = {v0, v1};
                    *(float2*)(Cb + (size_t)m * DIM + n) = o;
                } else {
                    Cb[(size_t)n * (BB * LDQ) + m] = v0;
                    Cb[(size_t)(n + 1) * (BB * LDQ) + m] = v1;
                }
            }
        }
    }
}

// ---------------- fused scores + mask + softmax (K streamed in 2 chunks) ----------------
#define STQ 68
#define SS_Q_FLOATS (32 * STQ)
#define SS_K_FLOATS (256 * STQ)
#define SS_SMEM_BYTES ((SS_Q_FLOATS + SS_K_FLOATS) * 4 + 512 * 4 + 32 * 8 * 4 + 32 * 4)

struct SSP {
    const float* Q;
    const float* K;
    const int* tok;
    float* S;
    int causal;
};

__global__ __launch_bounds__(256, 2) void scores_softmax(SSP p) {
    extern __shared__ float sm[];
    float* sQ = sm;
    float* sK = sm + SS_Q_FLOATS;
    int* stok = (int*)(sm + SS_Q_FLOATS + SS_K_FLOATS);
    float* red = (float*)(stok + 512);
    float* rowstat = red + 32 * 8;

    int tid = threadIdx.x, lane = tid & 31, w = tid >> 5;
    int bh = blockIdx.y;
    int b = bh / NH, h = bh % NH;
    int q0 = blockIdx.x * 32;

    const float* Qb = p.Q + (size_t)b * LDQ * DIM + (size_t)h * 64 + (size_t)q0 * DIM;
    const float* Kb = p.K + (size_t)b * LDQ * DIM + (size_t)h * 64;
    const int* tokb = p.tok + b * 512;

#pragma unroll
    for (int j = 0; j < 2; j++) {
        int i = tid + j * 256;
        int r = i >> 4, c4 = i & 15;
        cpa16(sQ + r * STQ + c4 * 4, Qb + (size_t)r * DIM + c4 * 4);
    }
#pragma unroll
    for (int j = 0; j < 16; j++) {
        int i = tid + j * 256;
        int r = i >> 4, c4 = i & 15;
        cpa16(sK + r * STQ + c4 * 4, Kb + (size_t)r * DIM + c4 * 4);
    }
    cpa_commit();
    stok[tid] = tokb[tid];
    stok[tid + 256] = tokb[tid + 256];
    cpa_wait0();
    __syncthreads();

    float acc[2][8][4];
#pragma unroll
    for (int mt = 0; mt < 2; mt++)
#pragma unroll
        for (int nt = 0; nt < 8; nt++)
#pragma unroll
            for (int i = 0; i < 4; i++) acc[mt][nt][i] = 0.f;

    for (int c = 0; c < 2; c++) {
#pragma unroll
        for (int ks = 0; ks < 8; ks++) {
            int kb = ks * 8 + (lane & 3);
            uint32_t af[2][4];
            int ar = lane >> 2;
#pragma unroll
            for (int mt = 0; mt < 2; mt++) {
                const float* ap = sQ + (ar + mt * 16) * STQ + kb;
                af[mt][0] = __float_as_uint(ap[0]);
                af[mt][1] = __float_as_uint(ap[8 * STQ]);
                af[mt][2] = __float_as_uint(ap[4]);
                af[mt][3] = __float_as_uint(ap[8 * STQ + 4]);
            }
            uint32_t bf[4][2];
            int br = w * 32 + (lane >> 2);
#pragma unroll
            for (int j = 0; j < 4; j++) {
                const float* bp = sK + (br + j * 8) * STQ + kb;
                bf[j][0] = __float_as_uint(bp[0]);
                bf[j][1] = __float_as_uint(bp[4]);
            }
#pragma unroll
            for (int mt = 0; mt < 2; mt++)
#pragma unroll
                for (int j = 0; j < 4; j++)
                    mma_tf32(acc[mt][c * 4 + j], af[mt], bf[j]);
        }
        if (c == 0) {
            __syncthreads();
#pragma unroll
            for (int j = 0; j < 16; j++) {
                int i = tid + j * 256;
                int r = i >> 4, c4 = i & 15;
                cpa16(sK + r * STQ + c4 * 4, Kb + (size_t)(256 + r) * DIM + c4 * 4);
            }
            cpa_commit();
            cpa_wait0();
            __syncthreads();
        }
    }

    float lmax[2][2] = {{-1e30f, -1e30f}, {-1e30f, -1e30f}};
#pragma unroll
    for (int mt = 0; mt < 2; mt++)
#pragma unroll
        for (int nt = 0; nt < 8; nt++)
#pragma unroll
            for (int j = 0; j < 4; j++) {
                int hf = j >> 1;
                int col = (nt >> 2) * 256 + w * 32 + (nt & 3) * 8 + (lane & 3) * 2 + (j & 1);
                int row = mt * 16 + (lane >> 2) + hf * 8;
                float v = acc[mt][nt][j] * 0.125f;
                bool msk = (stok[col] == 0) || (p.causal && col > q0 + row);
                v = msk ? -1e9f : v;
                acc[mt][nt][j] = v;
                lmax[mt][hf] = fmaxf(lmax[mt][hf], v);
            }
#pragma unroll
    for (int mt = 0; mt < 2; mt++)
#pragma unroll
        for (int hf = 0; hf < 2; hf++) {
            float v = lmax[mt][hf];
            v = fmaxf(v, __shfl_xor_sync(0xffffffffu, v, 1));
            v = fmaxf(v, __shfl_xor_sync(0xffffffffu, v, 2));
            lmax[mt][hf] = v;
        }
    if ((lane & 3) == 0) {
        int r0 = lane >> 2;
        red[(r0) * 8 + w] = lmax[0][0];
        red[(r0 + 8) * 8 + w] = lmax[0][1];
        red[(r0 + 16) * 8 + w] = lmax[1][0];
        red[(r0 + 24) * 8 + w] = lmax[1][1];
    }
    __syncthreads();
    if (tid < 32) {
        float m = red[tid * 8];
#pragma unroll
        for (int i = 1; i < 8; i++) m = fmaxf(m, red[tid * 8 + i]);
        rowstat[tid] = m;
    }
    __syncthreads();

    float rmax[2][2];
#pragma unroll
    for (int mt = 0; mt < 2; mt++)
#pragma unroll
        for (int hf = 0; hf < 2; hf++)
            rmax[mt][hf] = rowstat[mt * 16 + (lane >> 2) + hf * 8];
    __syncthreads();

    float lsum[2][2] = {{0.f, 0.f}, {0.f, 0.f}};
#pragma unroll
    for (int mt = 0; mt < 2; mt++)
#pragma unroll
        for (int nt = 0; nt < 8; nt++)
#pragma unroll
            for (int j = 0; j < 4; j++) {
                int hf = j >> 1;
                float e = expf(acc[mt][nt][j] - rmax[mt][hf]);
                acc[mt][nt][j] = e;
                lsum[mt][hf] += e;
            }
#pragma unroll
    for (int mt = 0; mt < 2; mt++)
#pragma unroll
        for (int hf = 0; hf < 2; hf++) {
            float v = lsum[mt][hf];
            v += __shfl_xor_sync(0xffffffffu, v, 1);
            v += __shfl_xor_sync(0xffffffffu, v, 2);
            lsum[mt][hf] = v;
        }
    if ((lane & 3) == 0) {
        int r0 = lane >> 2;
        red[(r0) * 8 + w] = lsum[0][0];
        red[(r0 + 8) * 8 + w] = lsum[0][1];
        red[(r0 + 16) * 8 + w] = lsum[1][0];
        red[(r0 + 24) * 8 + w] = lsum[1][1];
    }
    __syncthreads();
    if (tid < 32) {
        float s = 0.f;
#pragma unroll
        for (int i = 0; i < 8; i++) s += red[tid * 8 + i];
        rowstat[tid] = 1.f / s;
    }
    __syncthreads();

    float rinv[2][2];
#pragma unroll
    for (int mt = 0; mt < 2; mt++)
#pragma unroll
        for (int hf = 0; hf < 2; hf++)
            rinv[mt][hf] = rowstat[mt * 16 + (lane >> 2) + hf * 8];

    float* Sb = p.S + (size_t)bh * LDQ * 512;
#pragma unroll
    for (int mt = 0; mt < 2; mt++)
#pragma unroll
        for (int nt = 0; nt < 8; nt++)
#pragma unroll
            for (int hf = 0; hf < 2; hf++) {
                int row = q0 + mt * 16 + (lane >> 2) + hf * 8;
                int col = (nt >> 2) * 256 + w * 32 + (nt & 3) * 8 + (lane & 3) * 2;
                float2 o = {acc[mt][nt][hf * 2] * rinv[mt][hf],
                            acc[mt][nt][hf * 2 + 1] * rinv[mt][hf]};
                *(float2*)(Sb + (size_t)row * 512 + col) = o;
            }
}

// ---------------- fused (sum, sumsq) block reduction ----------------
__device__ __forceinline__ float2 blockReduceSum2(float s, float q, float* red) {
    int lane = threadIdx.x & 31, wid = threadIdx.x >> 5;
#pragma unroll
    for (int o = 16; o > 0; o >>= 1) {
        s += __shfl_xor_sync(0xffffffffu, s, o);
        q += __shfl_xor_sync(0xffffffffu, q, o);
    }
    if (lane == 0) { red[wid] = s; red[wid + 8] = q; }
    __syncthreads();
    float rs = 0.f, rq = 0.f;
    if (threadIdx.x < 8) { rs = red[threadIdx.x]; rq = red[threadIdx.x + 8]; }
    if (wid == 0) {
#pragma unroll
        for (int o = 4; o > 0; o >>= 1) {
            rs += __shfl_xor_sync(0xffu, rs, o);
            rq += __shfl_xor_sync(0xffu, rq, o);
        }
        if (lane == 0) { red[0] = rs; red[1] = rq; }
    }
    __syncthreads();
    float2 out = {red[0], red[1]};
    __syncthreads();
    return out;
}

// ---------------- embedding + sinusoidal position ----------------
__global__ __launch_bounds__(256) void embed_kernel(const int* __restrict__ dec,
                                                    const float* __restrict__ emb,
                                                    float* __restrict__ x,
                                                    float* __restrict__ xr) {
    int idx = blockIdx.x * 256 + threadIdx.x;
    if (idx >= BB * LDQ * DIM) return;
    int d = idx & (DIM - 1);
    int bl = idx / DIM;
    int l = bl & (LDQ - 1);
    int tok = dec[bl];
    double pos = (double)(l + 1);
    int jhalf = d >> 1;
    double denom = pow(10000.0, (double)(2 * jhalf) / (double)DIM);
    double a = pos / denom;
    float pe = ((d & 1) == 0) ? (float)sin(a) : (float)cos(a);
    float v = emb[(size_t)tok * DIM + d] + pe;
    x[idx] = v;
    xr[idx] = tf32r(v);
}

// ---------------- residual add + layernorm (single-pass moments; dual write) ----------------
__global__ __launch_bounds__(256) void add_ln(const float* __restrict__ A,
                                              const float* __restrict__ R,
                                              const float* __restrict__ g,
                                              const float* __restrict__ be,
                                              float* __restrict__ out,
                                              float* __restrict__ outr) {
    int row = blockIdx.x;
    int t = threadIdx.x;
    __shared__ float red[16];
    const float* a = A + (size_t)row * DIM;
    const float* r = R + (size_t)row * DIM;
    float x0 = a[t] + r[t];
    float x1 = a[t + 256] + r[t + 256];
    float2 mom = blockReduceSum2(x0 + x1, x0 * x0 + x1 * x1, red);
    float mean = mom.x * (1.f / 512.f);
    float var = mom.y * (1.f / 512.f) - mean * mean;
    float inv = rsqrtf(var + 1e-5f);
    float d0 = x0 - mean, d1 = x1 - mean;
    float o0 = d0 * inv * g[t] + be[t];
    float o1 = d1 * inv * g[t + 256] + be[t + 256];
    out[(size_t)row * DIM + t] = o0;
    out[(size_t)row * DIM + t + 256] = o1;
    outr[(size_t)row * DIM + t] = tf32r(o0);
    outr[(size_t)row * DIM + t + 256] = tf32r(o1);
}

// ---------------- host orchestration ----------------
#define SMEM128 (3 * (128 + 128) * 36 * 4)
#define SMEM64  (3 * (128 + 64) * 36 * 4)

struct Res {
    cudaStream_t s2;
    cudaEvent_t e1, eL[NLAY];
    Res() {
        cudaStreamCreateWithFlags(&s2, cudaStreamNonBlocking);
        cudaEventCreateWithFlags(&e1, cudaEventDisableTiming);
        for (int l = 0; l < NLAY; l++)
            cudaEventCreateWithFlags(&eL[l], cudaEventDisableTiming);
    }
};

extern "C" void kernel_launch(void* const* d_in, const int* in_sizes, int n_in,
                              void* d_out, int out_size) {
    static Res res;

    const int* dec = (const int*)d_in[0];
    const int* enc = (const int*)d_in[1];
    const float* enc_out = (const float*)d_in[2];
    const float* emb = (const float*)d_in[3];

    bool dict_order = (in_sizes[5] == NLAY * DIM * DIM);
    int iwq[2], iwk[2], iwv[2], iwo[2], ibq[2], ibk[2], ibv[2], ibo[2], ig[2], ib[2];
    for (int p = 0; p < 2; p++) {
        int base = 4 + p * 10;
        if (dict_order) {
            iwq[p] = base + 0; iwk[p] = base + 1; iwv[p] = base + 2; iwo[p] = base + 3;
            ibq[p] = base + 4; ibk[p] = base + 5; ibv[p] = base + 6; ibo[p] = base + 7;
            ig[p] = base + 8; ib[p] = base + 9;
        } else {
            iwq[p] = base + 0; ibq[p] = base + 1; iwk[p] = base + 2; ibk[p] = base + 3;
            iwv[p] = base + 4; ibv[p] = base + 5; iwo[p] = base + 6; ibo[p] = base + 7;
            ig[p] = base + 8; ib[p] = base + 9;
        }
    }
    const float* ffn_b1 = (const float*)d_in[25];
    const float* ffn_b2 = (const float*)d_in[27];
    const float* ffn_g = (const float*)d_in[28];
    const float* ffn_bb = (const float*)d_in[29];

    float *x, *xr, *encr, *q, *k, *vt, *ctxp, *proj, *ffh, *wr, *w1r, *w2r, *kca, *vtca;
    cudaGetSymbolAddress((void**)&x, g_x);
    cudaGetSymbolAddress((void**)&xr, g_xr);
    cudaGetSymbolAddress((void**)&encr, g_encr);
    cudaGetSymbolAddress((void**)&q, g_q);
    cudaGetSymbolAddress((void**)&k, g_k);
    cudaGetSymbolAddress((void**)&vt, g_vt);
    cudaGetSymbolAddress((void**)&ctxp, g_ctx);
    cudaGetSymbolAddress((void**)&proj, g_proj);
    cudaGetSymbolAddress((void**)&ffh, g_ffh);
    cudaGetSymbolAddress((void**)&wr, g_wr);
    cudaGetSymbolAddress((void**)&w1r, g_w1r);
    cudaGetSymbolAddress((void**)&w2r, g_w2r);
    cudaGetSymbolAddress((void**)&kca, g_kca);
    cudaGetSymbolAddress((void**)&vtca, g_vtca);

    cudaFuncSetAttribute(gemm_qkv, cudaFuncAttributeMaxDynamicSharedMemorySize, SMEM128);
    cudaFuncSetAttribute(gemm_kv, cudaFuncAttributeMaxDynamicSharedMemorySize, SMEM128);
    cudaFuncSetAttribute((const void*)gemm_std<128, false, true>,
                         cudaFuncAttributeMaxDynamicSharedMemorySize, SMEM128);
    cudaFuncSetAttribute((const void*)gemm_std<64, false, true>,
                         cudaFuncAttributeMaxDynamicSharedMemorySize, SMEM64);
    cudaFuncSetAttribute((const void*)gemm_std<64, true, true>,
                         cudaFuncAttributeMaxDynamicSharedMemorySize, SMEM64);
    cudaFuncSetAttribute((const void*)gemm_std<64, false, false>,
                         cudaFuncAttributeMaxDynamicSharedMemorySize, SMEM64);
    cudaFuncSetAttribute(scores_softmax, cudaFuncAttributeMaxDynamicSharedMemorySize, SS_SMEM_BYTES);

    float* out = (float*)d_out;
    const size_t XSZ = (size_t)BB * LDQ * DIM;
    const size_t AW = (size_t)BB * NH * LDQ * LDQ;
    float* sa_base = out + XSZ;
    float* ca_base = out + XSZ + (size_t)NLAY * AW;

    const int M = BB * LDQ;
    const long long LL = (long long)LDQ * LDQ;
    const int WSZ = NLAY * DIM * DIM;

    // main: round weights first
    {
        RC8 rc;
        for (int p = 0; p < 2; p++) {
            int idxs[4] = {iwq[p], iwk[p], iwv[p], iwo[p]};
            for (int j = 0; j < 4; j++) rc.src[p * 4 + j] = (const float*)d_in[idxs[j]];
        }
        rc.dst = wr;
        rc.n4 = WSZ / 4;
        round_copy8<<<dim3((rc.n4 + 255) / 256, 8), 256>>>(rc);
    }
    cudaEventRecord(res.e1, 0);

    // s2: encr round + all 6 CA K/V projections
    cudaStreamWaitEvent(res.s2, res.e1, 0);
    {
        int n4 = (BB * LDQ * DIM) / 4;
        round_copy<<<(n4 + 255) / 256, 256, 0, res.s2>>>(enc_out, encr, n4);
        for (int l = 0; l < NLAY; l++) {
            size_t wofs = (size_t)l * DIM * DIM;
            size_t bofs = (size_t)l * DIM;
            KVP kp;
            kp.A = encr;
            kp.W[0] = wr + (size_t)(1 * 4 + 1) * WSZ + wofs;
            kp.W[1] = wr + (size_t)(1 * 4 + 2) * WSZ + wofs;
            kp.bias[0] = (const float*)d_in[ibk[1]] + bofs;
            kp.bias[1] = (const float*)d_in[ibv[1]] + bofs;
            kp.C[0] = kca + (size_t)l * XSZ;
            kp.C[1] = vtca + (size_t)l * XSZ;
            gemm_kv<<<dim3(8, 32), 256, SMEM128, res.s2>>>(kp);
            cudaEventRecord(res.eL[l], res.s2);
        }
    }

    // main: remaining pre-rounds + embed
    {
        int f4 = (NLAY * FFD * DIM) / 4;
        round_copy<<<(f4 + 255) / 256, 256>>>((const float*)d_in[24], w1r, f4);
        round_copy<<<(f4 + 255) / 256, 256>>>((const float*)d_in[26], w2r, f4);
    }
    embed_kernel<<<(BB * LDQ * DIM + 255) / 256, 256>>>(dec, emb, x, xr);

    for (int l = 0; l < NLAY; l++) {
        size_t wofs = (size_t)l * DIM * DIM;
        size_t bofs = (size_t)l * DIM;

        for (int p = 0; p < 2; p++) {
            const float* wq = wr + (size_t)(p * 4 + 0) * WSZ + wofs;
            const float* wk = wr + (size_t)(p * 4 + 1) * WSZ + wofs;
            const float* wv = wr + (size_t)(p * 4 + 2) * WSZ + wofs;
            const float* wo = wr + (size_t)(p * 4 + 3) * WSZ + wofs;
            const float* bq = (const float*)d_in[ibq[p]] + bofs;
            const float* bk = (const float*)d_in[ibk[p]] + bofs;
            const float* bv = (const float*)d_in[ibv[p]] + bofs;
            const float* bo = (const float*)d_in[ibo[p]] + bofs;
            const float* gg = (const float*)d_in[ig[p]] + bofs;
            const float* bt = (const float*)d_in[ib[p]] + bofs;

            const int* tok = (p == 0) ? dec : enc;
            int causal = (p == 0) ? 1 : 0;
            float* S = ((p == 0) ? sa_base : ca_base) + (size_t)l * AW;

            const float* kuse;
            const float* vtuse;
            if (p == 0) {
                QKVP qp;
                qp.A[0] = xr; qp.A[1] = xr; qp.A[2] = xr;
                qp.W[0] = wq; qp.W[1] = wk; qp.W[2] = wv;
                qp.bias[0] = bq; qp.bias[1] = bk; qp.bias[2] = bv;
                qp.C[0] = q;  qp.C[1] = k;  qp.C[2] = vt;
                gemm_qkv<<<dim3(12, 32), 256, SMEM128>>>(qp);
                kuse = k; vtuse = vt;
            } else {
                GP gq = GP{xr, DIM, 0, 0, wq, DIM, 0, 0, q, DIM, 0, 0, bq, DIM, 0};
                gemm_std<64, false, true><<<dim3(8, 32, 1), 256, SMEM64>>>(gq);
                cudaStreamWaitEvent(0, res.eL[l], 0);
                kuse = kca + (size_t)l * XSZ;
                vtuse = vtca + (size_t)l * XSZ;
            }

            SSP sp{q, kuse, tok, S, causal};
            scores_softmax<<<dim3(16, BB * NH), 256, SS_SMEM_BYTES>>>(sp);

            GP gp;
            gp = GP{S, LDQ, NH * LL, LL, vtuse, M, LDQ, 64LL * M, ctxp, DIM, LL, 64,
                    nullptr, 512, 0};
            gemm_std<64, true, true><<<dim3(1, 4, BB * NH), 256, SMEM64>>>(gp);
            gp = GP{ctxp, DIM, 0, 0, wo, DIM, 0, 0, proj, DIM, 0, 0, bo, DIM, 0};
            gemm_std<64, false, false><<<dim3(8, 32, 1), 256, SMEM64>>>(gp);
            add_ln<<<M, 256>>>(proj, x, gg, bt, x, xr);
        }

        // FFN
        GP gp;
        gp = GP{xr, DIM, 0, 0, w1r + (size_t)l * FFD * DIM, DIM, 0, 0,
                ffh, FFD, 0, 0, ffn_b1 + (size_t)l * FFD, DIM, 1};
        gemm_std<128, false, true><<<dim3(16, 32, 1), 256, SMEM128>>>(gp);
        gp = GP{ffh, FFD, 0, 0, w2r + (size_t)l * DIM * FFD, FFD, 0, 0,
                proj, DIM, 0, 0, ffn_b2 + bofs, FFD, 0};
        gemm_std<64, false, false><<<dim3(8, 32, 1), 256, SMEM64>>>(gp);
        float* lnout = (l == NLAY - 1) ? out : x;
        add_ln<<<M, 256>>>(proj, x, ffn_g + bofs, ffn_bb + bofs, lnout, xr);
    }
}

// round 16
// speedup vs baseline: 1.0371x; 1.0043x over previous
#include <cuda_runtime.h>
#include <cstdint>
#include <math.h>

#define BB 8
#define LDQ 512
#define DIM 512
#define NH 8
#define FFD 2048
#define NLAY 6

// ---------------- scratch (static device globals; no allocation) ----------------
__device__ float g_x[BB * LDQ * DIM];
__device__ float g_xr[BB * LDQ * DIM];
__device__ float g_encr[BB * LDQ * DIM];
__device__ float g_q[BB * LDQ * DIM];
__device__ float g_k[BB * LDQ * DIM];
__device__ float g_vt[DIM * BB * LDQ];
__device__ float g_ctx[BB * LDQ * DIM];
__device__ float g_ffh[BB * LDQ * FFD];
__device__ float g_wr[8 * NLAY * DIM * DIM];
__device__ float g_w1r[NLAY * FFD * DIM];
__device__ float g_w2r[NLAY * DIM * FFD];
__device__ float g_kca[NLAY * BB * LDQ * DIM];
__device__ float g_vtca[NLAY * DIM * BB * LDQ];

// ---------------- small helpers ----------------
__device__ __forceinline__ float tf32r(float x) {
    uint32_t u;
    asm("cvt.rna.tf32.f32 %0, %1;" : "=r"(u) : "f"(x));
    return __uint_as_float(u);
}

__device__ __forceinline__ void mma_tf32(float* c, const uint32_t* a, const uint32_t* b) {
    asm volatile(
        "mma.sync.aligned.m16n8k8.row.col.f32.tf32.tf32.f32 "
        "{%0,%1,%2,%3}, {%4,%5,%6,%7}, {%8,%9}, {%0,%1,%2,%3};"
        : "+f"(c[0]), "+f"(c[1]), "+f"(c[2]), "+f"(c[3])
        : "r"(a[0]), "r"(a[1]), "r"(a[2]), "r"(a[3]), "r"(b[0]), "r"(b[1]));
}

__device__ __forceinline__ void cpa16(float* dst, const float* src) {
    asm volatile("cp.async.cg.shared.global [%0], [%1], 16;"
                 :: "r"((uint32_t)__cvta_generic_to_shared(dst)), "l"(src));
}
__device__ __forceinline__ void cpa_commit() {
    asm volatile("cp.async.commit_group;" ::: "memory");
}
__device__ __forceinline__ void cpa_wait1() {
    asm volatile("cp.async.wait_group 1;" ::: "memory");
}
__device__ __forceinline__ void cpa_wait0() {
    asm volatile("cp.async.wait_group 0;" ::: "memory");
}
#define CLUSTER_SYNC() do { \
    asm volatile("barrier.cluster.arrive.aligned;" ::: "memory"); \
    asm volatile("barrier.cluster.wait.aligned;" ::: "memory"); \
} while (0)

// ---------------- tf32 rounding copies ----------------
__global__ __launch_bounds__(256) void round_copy(const float* __restrict__ src,
                                                  float* __restrict__ dst, int n4) {
    int i = blockIdx.x * 256 + threadIdx.x;
    if (i >= n4) return;
    float4 v = ((const float4*)src)[i];
    v.x = tf32r(v.x); v.y = tf32r(v.y); v.z = tf32r(v.z); v.w = tf32r(v.w);
    ((float4*)dst)[i] = v;
}

struct RC8 { const float* src[8]; float* dst; int n4; };
__global__ __launch_bounds__(256) void round_copy8(RC8 p) {
    int i = blockIdx.x * 256 + threadIdx.x;
    if (i >= p.n4) return;
    float4 v = ((const float4*)p.src[blockIdx.y])[i];
    v.x = tf32r(v.x); v.y = tf32r(v.y); v.z = tf32r(v.z); v.w = tf32r(v.w);
    ((float4*)(p.dst + (size_t)blockIdx.y * p.n4 * 4))[i] = v;
}

// ---------------- core: 128 x BN tile, K-chunk 32, 3-stage cp.async ring ----------------
template <int BN, bool CVTA>
__device__ __forceinline__ void gemm_core(const float* __restrict__ Ab, long long lda,
                                          const float* __restrict__ Bb, long long ldb,
                                          int K, float* sm, int tid, int lane,
                                          int warp_m, int warp_n,
                                          float (&acc)[2][BN / 16][4]) {
    constexpr int ST = 36;
    constexpr int SLOT = (128 + BN) * ST;
    constexpr int NT = BN / 16;
    constexpr int BLD = BN / 32;

    float* slot0 = sm;
    float* slot1 = sm + SLOT;
    float* slot2 = sm + 2 * SLOT;

    const int nc = K >> 5;
    float4 rA[4];

    auto slotp = [&](int c) -> float* {
        int s = c % 3;
        return s == 0 ? slot0 : (s == 1 ? slot1 : slot2);
    };
    auto issue = [&](int c) {
        float* Ad = slotp(c);
        float* Bd = Ad + 128 * ST;
        int k0 = c << 5;
        if (!CVTA) {
#pragma unroll
            for (int j = 0; j < 4; j++) {
                int i = tid + j * 256;
                int r = i >> 3, c4 = i & 7;
                cpa16(Ad + r * ST + c4 * 4, Ab + (size_t)r * lda + k0 + c4 * 4);
            }
        }
#pragma unroll
        for (int j = 0; j < BLD; j++) {
            int i = tid + j * 256;
            int r = i >> 3, c4 = i & 7;
            cpa16(Bd + r * ST + c4 * 4, Bb + (size_t)r * ldb + k0 + c4 * 4);
        }
    };
    auto fetchA = [&](int c) {
        int k0 = c << 5;
#pragma unroll
        for (int j = 0; j < 4; j++) {
            int i = tid + j * 256;
            int r = i >> 3, c4 = i & 7;
            rA[j] = *(const float4*)(Ab + (size_t)r * lda + k0 + c4 * 4);
        }
    };
    auto stashA = [&](int c) {
        float* Ad = slotp(c);
#pragma unroll
        for (int j = 0; j < 4; j++) {
            int i = tid + j * 256;
            int r = i >> 3, c4 = i & 7;
            float* d = Ad + r * ST + c4 * 4;
            d[0] = tf32r(rA[j].x); d[1] = tf32r(rA[j].y);
            d[2] = tf32r(rA[j].z); d[3] = tf32r(rA[j].w);
        }
    };

    issue(0);
    cpa_commit();
    issue(1);
    cpa_commit();
    if (CVTA) {
        fetchA(0); stashA(0);
        fetchA(1); stashA(1);
    }
    cpa_wait1();
    __syncthreads();

    for (int c = 0; c < nc; c++) {
        bool more2 = (c + 2 < nc);
        if (more2) issue(c + 2);
        cpa_commit();
        if (CVTA && more2) fetchA(c + 2);

        float* Ac = slotp(c);
        float* Bc = Ac + 128 * ST;
#pragma unroll
        for (int ks = 0; ks < 4; ks++) {
            int kb = ks * 8 + (lane & 3);
            uint32_t af[2][4];
            int ar = warp_m * 32 + (lane >> 2);
#pragma unroll
            for (int mt = 0; mt < 2; mt++) {
                const float* ap = Ac + (ar + mt * 16) * ST + kb;
                af[mt][0] = __float_as_uint(ap[0]);
                af[mt][1] = __float_as_uint(ap[8 * ST]);
                af[mt][2] = __float_as_uint(ap[4]);
                af[mt][3] = __float_as_uint(ap[8 * ST + 4]);
            }
            uint32_t bf[NT][2];
            int br = warp_n * (NT * 8) + (lane >> 2);
#pragma unroll
            for (int nt = 0; nt < NT; nt++) {
                const float* bp = Bc + (br + nt * 8) * ST + kb;
                bf[nt][0] = __float_as_uint(bp[0]);
                bf[nt][1] = __float_as_uint(bp[4]);
            }
#pragma unroll
            for (int mt = 0; mt < 2; mt++)
#pragma unroll
                for (int nt = 0; nt < NT; nt++)
                    mma_tf32(acc[mt][nt], af[mt], bf[nt]);
        }

        if (CVTA && more2) stashA(c + 2);
        cpa_wait1();
        __syncthreads();
    }
    cpa_wait0();
}

struct GP {
    const float* A; long long lda, aB, aH;
    const float* B; long long ldb, bB, bH;
    float* C;       long long ldc, cB, cH;
    const float* bias;
    int K, relu;
};

template <int BN, bool CVTA, bool RO>
__global__ __launch_bounds__(256, 2) void gemm_std(GP p) {
    extern __shared__ float sm[];
    constexpr int NT = BN / 16;
    int tid = threadIdx.x, lane = tid & 31, wid = tid >> 5;
    int warp_m = wid & 3, warp_n = wid >> 2;
    int b = blockIdx.z / NH, h = blockIdx.z % NH;

    const float* Ab = p.A + (size_t)b * p.aB + (size_t)h * p.aH +
                      (size_t)(blockIdx.y * 128) * p.lda;
    const float* Bb = p.B + (size_t)b * p.bB + (size_t)h * p.bH +
                      (size_t)(blockIdx.x * BN) * p.ldb;

    float acc[2][NT][4];
#pragma unroll
    for (int mt = 0; mt < 2; mt++)
#pragma unroll
        for (int nt = 0; nt < NT; nt++)
#pragma unroll
            for (int i = 0; i < 4; i++) acc[mt][nt][i] = 0.f;

    gemm_core<BN, CVTA>(Ab, p.lda, Bb, p.ldb, p.K, sm, tid, lane, warp_m, warp_n, acc);

    float* Cb = p.C + (size_t)b * p.cB + (size_t)h * p.cH;
    int mbase = blockIdx.y * 128 + warp_m * 32 + (lane >> 2);
    int nbase = blockIdx.x * BN + warp_n * (NT * 8) + (lane & 3) * 2;

#pragma unroll
    for (int mt = 0; mt < 2; mt++) {
#pragma unroll
        for (int nt = 0; nt < NT; nt++) {
            int n = nbase + nt * 8;
#pragma unroll
            for (int hf = 0; hf < 2; hf++) {
                int m = mbase + mt * 16 + hf * 8;
                float v0 = acc[mt][nt][hf * 2];
                float v1 = acc[mt][nt][hf * 2 + 1];
                if (p.bias) { v0 += p.bias[n]; v1 += p.bias[n + 1]; }
                if (p.relu) { v0 = fmaxf(v0, 0.f); v1 = fmaxf(v1, 0.f); }
                if (RO) { v0 = tf32r(v0); v1 = tf32r(v1); }
                float2 o = {v0, v1};
                *(float2*)(Cb + (size_t)m * p.ldc + n) = o;
            }
        }
    }
}

// ---------------- cluster-fused GEMM + residual + LayerNorm ----------------
// Cluster of 8 x-blocks covers the full 512 columns of a 128-row block.
// out = LN(A*B^T + bias + R) * g + be ; outr = tf32(out).
struct GLP {
    const float* A;     // [4096, K] rounded
    const float* B;     // [512, K] rounded weights
    const float* bias;  // [512]
    const float* R;     // [4096, 512] residual (full precision)
    const float* g;
    const float* be;
    float* out;         // [4096, 512]
    float* outr;        // [4096, 512] rounded
    int K;
};

#define GLN_RINGF (3 * (128 + 64) * 36)
#define GLN_SMEM ((GLN_RINGF + 1024) * 4)

__global__ __launch_bounds__(256, 2) __cluster_dims__(8, 1, 1)
void gemm_ln(GLP p) {
    extern __shared__ float sm[];
    constexpr int BN = 64, NT = 4;
    float* sS = sm + GLN_RINGF;              // [128][2]
    float* sQ = sS + 256;                    // [128][2]
    float2* sPart = (float2*)(sQ + 256);     // [128]
    float2* sMV = sPart + 128;               // [128]

    int tid = threadIdx.x, lane = tid & 31, wid = tid >> 5;
    int warp_m = wid & 3, warp_n = wid >> 2;

    const float* Ab = p.A + (size_t)(blockIdx.y * 128) * p.K;
    const float* Bb = p.B + (size_t)(blockIdx.x * BN) * p.K;

    float acc[2][NT][4];
#pragma unroll
    for (int mt = 0; mt < 2; mt++)
#pragma unroll
        for (int nt = 0; nt < NT; nt++)
#pragma unroll
            for (int i = 0; i < 4; i++) acc[mt][nt][i] = 0.f;

    gemm_core<BN, false>(Ab, p.K, Bb, p.K, p.K, sm, tid, lane, warp_m, warp_n, acc);

    int mbase = blockIdx.y * 128 + warp_m * 32 + (lane >> 2);
    int nbase = blockIdx.x * BN + warp_n * (NT * 8) + (lane & 3) * 2;

    // bias + residual; per-row partial moments
    float ls[2][2] = {{0.f, 0.f}, {0.f, 0.f}};
    float lq[2][2] = {{0.f, 0.f}, {0.f, 0.f}};
#pragma unroll
    for (int mt = 0; mt < 2; mt++)
#pragma unroll
        for (int nt = 0; nt < NT; nt++) {
            int n = nbase + nt * 8;
#pragma unroll
            for (int hf = 0; hf < 2; hf++) {
                int m = mbase + mt * 16 + hf * 8;
                float2 rr = *(const float2*)(p.R + (size_t)m * DIM + n);
                float v0 = acc[mt][nt][hf * 2] + p.bias[n] + rr.x;
                float v1 = acc[mt][nt][hf * 2 + 1] + p.bias[n + 1] + rr.y;
                acc[mt][nt][hf * 2] = v0;
                acc[mt][nt][hf * 2 + 1] = v1;
                ls[mt][hf] += v0 + v1;
                lq[mt][hf] += v0 * v0 + v1 * v1;
            }
        }
#pragma unroll
    for (int mt = 0; mt < 2; mt++)
#pragma unroll
        for (int hf = 0; hf < 2; hf++) {
            float s = ls[mt][hf], q = lq[mt][hf];
            s += __shfl_xor_sync(0xffffffffu, s, 1);
            q += __shfl_xor_sync(0xffffffffu, q, 1);
            s += __shfl_xor_sync(0xffffffffu, s, 2);
            q += __shfl_xor_sync(0xffffffffu, q, 2);
            if ((lane & 3) == 0) {
                int rl = warp_m * 32 + mt * 16 + hf * 8 + (lane >> 2);
                sS[rl * 2 + warp_n] = s;
                sQ[rl * 2 + warp_n] = q;
            }
        }
    __syncthreads();
    if (tid < 128) {
        float2 v = {sS[tid * 2] + sS[tid * 2 + 1], sQ[tid * 2] + sQ[tid * 2 + 1]};
        sPart[tid] = v;
    }
    __syncthreads();
    CLUSTER_SYNC();

    // sum partials across the 8 cluster blocks via DSMEM
    if (tid < 128) {
        uint32_t la = (uint32_t)__cvta_generic_to_shared(&sPart[tid]);
        float s = 0.f, q = 0.f;
#pragma unroll
        for (int cb = 0; cb < 8; cb++) {
            uint32_t ra;
            asm("mapa.shared::cluster.u32 %0, %1, %2;" : "=r"(ra) : "r"(la), "r"(cb));
            unsigned long long d;
            asm("ld.shared::cluster.b64 %0, [%1];" : "=l"(d) : "r"(ra));
            float2 v = *(float2*)&d;
            s += v.x; q += v.y;
        }
        float mean = s * (1.f / 512.f);
        float var = q * (1.f / 512.f) - mean * mean;
        float2 mv = {mean, rsqrtf(var + 1e-5f)};
        sMV[tid] = mv;
    }
    __syncthreads();

    // normalize + write out / outr
#pragma unroll
    for (int mt = 0; mt < 2; mt++)
#pragma unroll
        for (int hf = 0; hf < 2; hf++) {
            int rl = warp_m * 32 + mt * 16 + hf * 8 + (lane >> 2);
            float2 mv = sMV[rl];
            int m = mbase + mt * 16 + hf * 8;
#pragma unroll
            for (int nt = 0; nt < NT; nt++) {
                int n = nbase + nt * 8;
                float o0 = (acc[mt][nt][hf * 2] - mv.x) * mv.y * p.g[n] + p.be[n];
                float o1 = (acc[mt][nt][hf * 2 + 1] - mv.x) * mv.y * p.g[n + 1] + p.be[n + 1];
                float2 o = {o0, o1};
                *(float2*)(p.out + (size_t)m * DIM + n) = o;
                float2 orr = {tf32r(o0), tf32r(o1)};
                *(float2*)(p.outr + (size_t)m * DIM + n) = orr;
            }
        }
    CLUSTER_SYNC();   // no block exits while peers may still read its SMEM
}

// ---------------- fused QKV projection (128x128 tiles) ----------------
struct QKVP {
    const float* A[3];
    const float* W[3];
    const float* bias[3];
    float* C[3];
};

__global__ __launch_bounds__(256, 2) void gemm_qkv(QKVP p) {
    extern __shared__ float sm[];
    constexpr int BN = 128, NT = 8;
    int tid = threadIdx.x, lane = tid & 31, wid = tid >> 5;
    int warp_m = wid & 3, warp_n = wid >> 2;
    int sel = blockIdx.x >> 2;
    int nblk = blockIdx.x & 3;

    const float* Ab = p.A[sel] + (size_t)(blockIdx.y * 128) * DIM;
    const float* Bb = p.W[sel] + (size_t)(nblk * BN) * DIM;

    float acc[2][NT][4];
#pragma unroll
    for (int mt = 0; mt < 2; mt++)
#pragma unroll
        for (int nt = 0; nt < NT; nt++)
#pragma unroll
            for (int i = 0; i < 4; i++) acc[mt][nt][i] = 0.f;

    gemm_core<BN, false>(Ab, DIM, Bb, DIM, DIM, sm, tid, lane, warp_m, warp_n, acc);

    const float* bias = p.bias[sel];
    float* Cb = p.C[sel];
    int mbase = blockIdx.y * 128 + warp_m * 32 + (lane >> 2);
    int nbase = nblk * BN + warp_n * (NT * 8) + (lane & 3) * 2;

#pragma unroll
    for (int mt = 0; mt < 2; mt++) {
#pragma unroll
        for (int nt = 0; nt < NT; nt++) {
            int n = nbase + nt * 8;
#pragma unroll
            for (int hf = 0; hf < 2; hf++) {
                int m = mbase + mt * 16 + hf * 8;
                float v0 = tf32r(acc[mt][nt][hf * 2] + bias[n]);
                float v1 = tf32r(acc[mt][nt][hf * 2 + 1] + bias[n + 1]);
                if (sel < 2) {
                    float2 o = {v0, v1};
                    *(float2*)(Cb + (size_t)m * DIM + n) = o;
                } else {
                    Cb[(size_t)n * (BB * LDQ) + m] = v0;
                    Cb[(size_t)(n + 1) * (BB * LDQ) + m] = v1;
                }
            }
        }
    }
}

// ---------------- CA K/V projection (side stream) ----------------
struct KVP {
    const float* A;
    const float* W[2];
    const float* bias[2];
    float* C[2];
};

__global__ __launch_bounds__(256, 2) void gemm_kv(KVP p) {
    extern __shared__ float sm[];
    constexpr int BN = 128, NT = 8;
    int tid = threadIdx.x, lane = tid & 31, wid = tid >> 5;
    int warp_m = wid & 3, warp_n = wid >> 2;
    int sel = blockIdx.x >> 2;
    int nblk = blockIdx.x & 3;

    const float* Ab = p.A + (size_t)(blockIdx.y * 128) * DIM;
    const float* Bb = p.W[sel] + (size_t)(nblk * BN) * DIM;

    float acc[2][NT][4];
#pragma unroll
    for (int mt = 0; mt < 2; mt++)
#pragma unroll
        for (int nt = 0; nt < NT; nt++)
#pragma unroll
            for (int i = 0; i < 4; i++) acc[mt][nt][i] = 0.f;

    gemm_core<BN, false>(Ab, DIM, Bb, DIM, DIM, sm, tid, lane, warp_m, warp_n, acc);

    const float* bias = p.bias[sel];
    float* Cb = p.C[sel];
    int mbase = blockIdx.y * 128 + warp_m * 32 + (lane >> 2);
    int nbase = nblk * BN + warp_n * (NT * 8) + (lane & 3) * 2;

#pragma unroll
    for (int mt = 0; mt < 2; mt++) {
#pragma unroll
        for (int nt = 0; nt < NT; nt++) {
            int n = nbase + nt * 8;
#pragma unroll
            for (int hf = 0; hf < 2; hf++) {
                int m = mbase + mt * 16 + hf * 8;
                float v0 = tf32r(acc[mt][nt][hf * 2] + bias[n]);
                float v1 = tf32r(acc[mt][nt][hf * 2 + 1] + bias[n + 1]);
                if (sel == 0) {
                    float2 o = {v0, v1};
                    *(float2*)(Cb + (size_t)m * DIM + n) = o;
                } else {
                    Cb[(size_t)n * (BB * LDQ) + m] = v0;
                    Cb[(size_t)(n + 1) * (BB * LDQ) + m] = v1;
                }
            }
        }
    }
}

// ---------------- fused scores + mask + softmax (K streamed in 2 chunks) ----------------
#define STQ 68
#define SS_Q_FLOATS (32 * STQ)
#define SS_K_FLOATS (256 * STQ)
#define SS_SMEM_BYTES ((SS_Q_FLOATS + SS_K_FLOATS) * 4 + 512 * 4 + 32 * 8 * 4 + 32 * 4)

struct SSP {
    const float* Q;
    const float* K;
    const int* tok;
    float* S;
    int causal;
};

__global__ __launch_bounds__(256, 2) void scores_softmax(SSP p) {
    extern __shared__ float sm[];
    float* sQ = sm;
    float* sK = sm + SS_Q_FLOATS;
    int* stok = (int*)(sm + SS_Q_FLOATS + SS_K_FLOATS);
    float* red = (float*)(stok + 512);
    float* rowstat = red + 32 * 8;

    int tid = threadIdx.x, lane = tid & 31, w = tid >> 5;
    int bh = blockIdx.y;
    int b = bh / NH, h = bh % NH;
    int q0 = blockIdx.x * 32;

    const float* Qb = p.Q + (size_t)b * LDQ * DIM + (size_t)h * 64 + (size_t)q0 * DIM;
    const float* Kb = p.K + (size_t)b * LDQ * DIM + (size_t)h * 64;
    const int* tokb = p.tok + b * 512;

#pragma unroll
    for (int j = 0; j < 2; j++) {
        int i = tid + j * 256;
        int r = i >> 4, c4 = i & 15;
        cpa16(sQ + r * STQ + c4 * 4, Qb + (size_t)r * DIM + c4 * 4);
    }
#pragma unroll
    for (int j = 0; j < 16; j++) {
        int i = tid + j * 256;
        int r = i >> 4, c4 = i & 15;
        cpa16(sK + r * STQ + c4 * 4, Kb + (size_t)r * DIM + c4 * 4);
    }
    cpa_commit();
    stok[tid] = tokb[tid];
    stok[tid + 256] = tokb[tid + 256];
    cpa_wait0();
    __syncthreads();

    float acc[2][8][4];
#pragma unroll
    for (int mt = 0; mt < 2; mt++)
#pragma unroll
        for (int nt = 0; nt < 8; nt++)
#pragma unroll
            for (int i = 0; i < 4; i++) acc[mt][nt][i] = 0.f;

    for (int c = 0; c < 2; c++) {
#pragma unroll
        for (int ks = 0; ks < 8; ks++) {
            int kb = ks * 8 + (lane & 3);
            uint32_t af[2][4];
            int ar = lane >> 2;
#pragma unroll
            for (int mt = 0; mt < 2; mt++) {
                const float* ap = sQ + (ar + mt * 16) * STQ + kb;
                af[mt][0] = __float_as_uint(ap[0]);
                af[mt][1] = __float_as_uint(ap[8 * STQ]);
                af[mt][2] = __float_as_uint(ap[4]);
                af[mt][3] = __float_as_uint(ap[8 * STQ + 4]);
            }
            uint32_t bf[4][2];
            int br = w * 32 + (lane >> 2);
#pragma unroll
            for (int j = 0; j < 4; j++) {
                const float* bp = sK + (br + j * 8) * STQ + kb;
                bf[j][0] = __float_as_uint(bp[0]);
                bf[j][1] = __float_as_uint(bp[4]);
            }
#pragma unroll
            for (int mt = 0; mt < 2; mt++)
#pragma unroll
                for (int j = 0; j < 4; j++)
                    mma_tf32(acc[mt][c * 4 + j], af[mt], bf[j]);
        }
        if (c == 0) {
            __syncthreads();
#pragma unroll
            for (int j = 0; j < 16; j++) {
                int i = tid + j * 256;
                int r = i >> 4, c4 = i & 15;
                cpa16(sK + r * STQ + c4 * 4, Kb + (size_t)(256 + r) * DIM + c4 * 4);
            }
            cpa_commit();
            cpa_wait0();
            __syncthreads();
        }
    }

    float lmax[2][2] = {{-1e30f, -1e30f}, {-1e30f, -1e30f}};
#pragma unroll
    for (int mt = 0; mt < 2; mt++)
#pragma unroll
        for (int nt = 0; nt < 8; nt++)
#pragma unroll
            for (int j = 0; j < 4; j++) {
                int hf = j >> 1;
                int col = (nt >> 2) * 256 + w * 32 + (nt & 3) * 8 + (lane & 3) * 2 + (j & 1);
                int row = mt * 16 + (lane >> 2) + hf * 8;
                float v = acc[mt][nt][j] * 0.125f;
                bool msk = (stok[col] == 0) || (p.causal && col > q0 + row);
                v = msk ? -1e9f : v;
                acc[mt][nt][j] = v;
                lmax[mt][hf] = fmaxf(lmax[mt][hf], v);
            }
#pragma unroll
    for (int mt = 0; mt < 2; mt++)
#pragma unroll
        for (int hf = 0; hf < 2; hf++) {
            float v = lmax[mt][hf];
            v = fmaxf(v, __shfl_xor_sync(0xffffffffu, v, 1));
            v = fmaxf(v, __shfl_xor_sync(0xffffffffu, v, 2));
            lmax[mt][hf] = v;
        }
    if ((lane & 3) == 0) {
        int r0 = lane >> 2;
        red[(r0) * 8 + w] = lmax[0][0];
        red[(r0 + 8) * 8 + w] = lmax[0][1];
        red[(r0 + 16) * 8 + w] = lmax[1][0];
        red[(r0 + 24) * 8 + w] = lmax[1][1];
    }
    __syncthreads();
    if (tid < 32) {
        float m = red[tid * 8];
#pragma unroll
        for (int i = 1; i < 8; i++) m = fmaxf(m, red[tid * 8 + i]);
        rowstat[tid] = m;
    }
    __syncthreads();

    float rmax[2][2];
#pragma unroll
    for (int mt = 0; mt < 2; mt++)
#pragma unroll
        for (int hf = 0; hf < 2; hf++)
            rmax[mt][hf] = rowstat[mt * 16 + (lane >> 2) + hf * 8];
    __syncthreads();

    float lsum[2][2] = {{0.f, 0.f}, {0.f, 0.f}};
#pragma unroll
    for (int mt = 0; mt < 2; mt++)
#pragma unroll
        for (int nt = 0; nt < 8; nt++)
#pragma unroll
            for (int j = 0; j < 4; j++) {
                int hf = j >> 1;
                float e = expf(acc[mt][nt][j] - rmax[mt][hf]);
                acc[mt][nt][j] = e;
                lsum[mt][hf] += e;
            }
#pragma unroll
    for (int mt = 0; mt < 2; mt++)
#pragma unroll
        for (int hf = 0; hf < 2; hf++) {
            float v = lsum[mt][hf];
            v += __shfl_xor_sync(0xffffffffu, v, 1);
            v += __shfl_xor_sync(0xffffffffu, v, 2);
            lsum[mt][hf] = v;
        }
    if ((lane & 3) == 0) {
        int r0 = lane >> 2;
        red[(r0) * 8 + w] = lsum[0][0];
        red[(r0 + 8) * 8 + w] = lsum[0][1];
        red[(r0 + 16) * 8 + w] = lsum[1][0];
        red[(r0 + 24) * 8 + w] = lsum[1][1];
    }
    __syncthreads();
    if (tid < 32) {
        float s = 0.f;
#pragma unroll
        for (int i = 0; i < 8; i++) s += red[tid * 8 + i];
        rowstat[tid] = 1.f / s;
    }
    __syncthreads();

    float rinv[2][2];
#pragma unroll
    for (int mt = 0; mt < 2; mt++)
#pragma unroll
        for (int hf = 0; hf < 2; hf++)
            rinv[mt][hf] = rowstat[mt * 16 + (lane >> 2) + hf * 8];

    float* Sb = p.S + (size_t)bh * LDQ * 512;
#pragma unroll
    for (int mt = 0; mt < 2; mt++)
#pragma unroll
        for (int nt = 0; nt < 8; nt++)
#pragma unroll
            for (int hf = 0; hf < 2; hf++) {
                int row = q0 + mt * 16 + (lane >> 2) + hf * 8;
                int col = (nt >> 2) * 256 + w * 32 + (nt & 3) * 8 + (lane & 3) * 2;
                float2 o = {acc[mt][nt][hf * 2] * rinv[mt][hf],
                            acc[mt][nt][hf * 2 + 1] * rinv[mt][hf]};
                *(float2*)(Sb + (size_t)row * 512 + col) = o;
            }
}

// ---------------- embedding + sinusoidal position ----------------
__global__ __launch_bounds__(256) void embed_kernel(const int* __restrict__ dec,
                                                    const float* __restrict__ emb,
                                                    float* __restrict__ x,
                                                    float* __restrict__ xr) {
    int idx = blockIdx.x * 256 + threadIdx.x;
    if (idx >= BB * LDQ * DIM) return;
    int d = idx & (DIM - 1);
    int bl = idx / DIM;
    int l = bl & (LDQ - 1);
    int tok = dec[bl];
    double pos = (double)(l + 1);
    int jhalf = d >> 1;
    double denom = pow(10000.0, (double)(2 * jhalf) / (double)DIM);
    double a = pos / denom;
    float pe = ((d & 1) == 0) ? (float)sin(a) : (float)cos(a);
    float v = emb[(size_t)tok * DIM + d] + pe;
    x[idx] = v;
    xr[idx] = tf32r(v);
}

// ---------------- host orchestration ----------------
#define SMEM128 (3 * (128 + 128) * 36 * 4)
#define SMEM64  (3 * (128 + 64) * 36 * 4)

struct Res {
    cudaStream_t s2;
    cudaEvent_t e1, eL[NLAY];
    Res() {
        cudaStreamCreateWithFlags(&s2, cudaStreamNonBlocking);
        cudaEventCreateWithFlags(&e1, cudaEventDisableTiming);
        for (int l = 0; l < NLAY; l++)
            cudaEventCreateWithFlags(&eL[l], cudaEventDisableTiming);
    }
};

extern "C" void kernel_launch(void* const* d_in, const int* in_sizes, int n_in,
                              void* d_out, int out_size) {
    static Res res;

    const int* dec = (const int*)d_in[0];
    const int* enc = (const int*)d_in[1];
    const float* enc_out = (const float*)d_in[2];
    const float* emb = (const float*)d_in[3];

    bool dict_order = (in_sizes[5] == NLAY * DIM * DIM);
    int iwq[2], iwk[2], iwv[2], iwo[2], ibq[2], ibk[2], ibv[2], ibo[2], ig[2], ib[2];
    for (int p = 0; p < 2; p++) {
        int base = 4 + p * 10;
        if (dict_order) {
            iwq[p] = base + 0; iwk[p] = base + 1; iwv[p] = base + 2; iwo[p] = base + 3;
            ibq[p] = base + 4; ibk[p] = base + 5; ibv[p] = base + 6; ibo[p] = base + 7;
            ig[p] = base + 8; ib[p] = base + 9;
        } else {
            iwq[p] = base + 0; ibq[p] = base + 1; iwk[p] = base + 2; ibk[p] = base + 3;
            iwv[p] = base + 4; ibv[p] = base + 5; iwo[p] = base + 6; ibo[p] = base + 7;
            ig[p] = base + 8; ib[p] = base + 9;
        }
    }
    const float* ffn_b1 = (const float*)d_in[25];
    const float* ffn_b2 = (const float*)d_in[27];
    const float* ffn_g = (const float*)d_in[28];
    const float* ffn_bb = (const float*)d_in[29];

    float *x, *xr, *encr, *q, *k, *vt, *ctxp, *ffh, *wr, *w1r, *w2r, *kca, *vtca;
    cudaGetSymbolAddress((void**)&x, g_x);
    cudaGetSymbolAddress((void**)&xr, g_xr);
    cudaGetSymbolAddress((void**)&encr, g_encr);
    cudaGetSymbolAddress((void**)&q, g_q);
    cudaGetSymbolAddress((void**)&k, g_k);
    cudaGetSymbolAddress((void**)&vt, g_vt);
    cudaGetSymbolAddress((void**)&ctxp, g_ctx);
    cudaGetSymbolAddress((void**)&ffh, g_ffh);
    cudaGetSymbolAddress((void**)&wr, g_wr);
    cudaGetSymbolAddress((void**)&w1r, g_w1r);
    cudaGetSymbolAddress((void**)&w2r, g_w2r);
    cudaGetSymbolAddress((void**)&kca, g_kca);
    cudaGetSymbolAddress((void**)&vtca, g_vtca);

    cudaFuncSetAttribute(gemm_qkv, cudaFuncAttributeMaxDynamicSharedMemorySize, SMEM128);
    cudaFuncSetAttribute(gemm_kv, cudaFuncAttributeMaxDynamicSharedMemorySize, SMEM128);
    cudaFuncSetAttribute(gemm_ln, cudaFuncAttributeMaxDynamicSharedMemorySize, GLN_SMEM);
    cudaFuncSetAttribute((const void*)gemm_std<128, false, true>,
                         cudaFuncAttributeMaxDynamicSharedMemorySize, SMEM128);
    cudaFuncSetAttribute((const void*)gemm_std<64, false, true>,
                         cudaFuncAttributeMaxDynamicSharedMemorySize, SMEM64);
    cudaFuncSetAttribute((const void*)gemm_std<64, true, true>,
                         cudaFuncAttributeMaxDynamicSharedMemorySize, SMEM64);
    cudaFuncSetAttribute(scores_softmax, cudaFuncAttributeMaxDynamicSharedMemorySize, SS_SMEM_BYTES);

    float* out = (float*)d_out;
    const size_t XSZ = (size_t)BB * LDQ * DIM;
    const size_t AW = (size_t)BB * NH * LDQ * LDQ;
    float* sa_base = out + XSZ;
    float* ca_base = out + XSZ + (size_t)NLAY * AW;

    const int M = BB * LDQ;
    const long long LL = (long long)LDQ * LDQ;
    const int WSZ = NLAY * DIM * DIM;

    // main: round weights first
    {
        RC8 rc;
        for (int p = 0; p < 2; p++) {
            int idxs[4] = {iwq[p], iwk[p], iwv[p], iwo[p]};
            for (int j = 0; j < 4; j++) rc.src[p * 4 + j] = (const float*)d_in[idxs[j]];
        }
        rc.dst = wr;
        rc.n4 = WSZ / 4;
        round_copy8<<<dim3((rc.n4 + 255) / 256, 8), 256>>>(rc);
    }
    cudaEventRecord(res.e1, 0);

    // s2: encr round + all 6 CA K/V projections
    cudaStreamWaitEvent(res.s2, res.e1, 0);
    {
        int n4 = (BB * LDQ * DIM) / 4;
        round_copy<<<(n4 + 255) / 256, 256, 0, res.s2>>>(enc_out, encr, n4);
        for (int l = 0; l < NLAY; l++) {
            size_t wofs = (size_t)l * DIM * DIM;
            size_t bofs = (size_t)l * DIM;
            KVP kp;
            kp.A = encr;
            kp.W[0] = wr + (size_t)(1 * 4 + 1) * WSZ + wofs;
            kp.W[1] = wr + (size_t)(1 * 4 + 2) * WSZ + wofs;
            kp.bias[0] = (const float*)d_in[ibk[1]] + bofs;
            kp.bias[1] = (const float*)d_in[ibv[1]] + bofs;
            kp.C[0] = kca + (size_t)l * XSZ;
            kp.C[1] = vtca + (size_t)l * XSZ;
            gemm_kv<<<dim3(8, 32), 256, SMEM128, res.s2>>>(kp);
            cudaEventRecord(res.eL[l], res.s2);
        }
    }

    // main: remaining pre-rounds + embed
    {
        int f4 = (NLAY * FFD * DIM) / 4;
        round_copy<<<(f4 + 255) / 256, 256>>>((const float*)d_in[24], w1r, f4);
        round_copy<<<(f4 + 255) / 256, 256>>>((const float*)d_in[26], w2r, f4);
    }
    embed_kernel<<<(BB * LDQ * DIM + 255) / 256, 256>>>(dec, emb, x, xr);

    for (int l = 0; l < NLAY; l++) {
        size_t wofs = (size_t)l * DIM * DIM;
        size_t bofs = (size_t)l * DIM;

        for (int p = 0; p < 2; p++) {
            const float* wq = wr + (size_t)(p * 4 + 0) * WSZ + wofs;
            const float* wk = wr + (size_t)(p * 4 + 1) * WSZ + wofs;
            const float* wv = wr + (size_t)(p * 4 + 2) * WSZ + wofs;
            const float* wo = wr + (size_t)(p * 4 + 3) * WSZ + wofs;
            const float* bq = (const float*)d_in[ibq[p]] + bofs;
            const float* bk = (const float*)d_in[ibk[p]] + bofs;
            const float* bv = (const float*)d_in[ibv[p]] + bofs;
            const float* bo = (const float*)d_in[ibo[p]] + bofs;
            const float* gg = (const float*)d_in[ig[p]] + bofs;
            const float* bt = (const float*)d_in[ib[p]] + bofs;

            const int* tok = (p == 0) ? dec : enc;
            int causal = (p == 0) ? 1 : 0;
            float* S = ((p == 0) ? sa_base : ca_base) + (size_t)l * AW;

            const float* kuse;
            const float* vtuse;
            if (p == 0) {
                QKVP qp;
                qp.A[0] = xr; qp.A[1] = xr; qp.A[2] = xr;
                qp.W[0] = wq; qp.W[1] = wk; qp.W[2] = wv;
                qp.bias[0] = bq; qp.bias[1] = bk; qp.bias[2] = bv;
                qp.C[0] = q;  qp.C[1] = k;  qp.C[2] = vt;
                gemm_qkv<<<dim3(12, 32), 256, SMEM128>>>(qp);
                kuse = k; vtuse = vt;
            } else {
                GP gq = GP{xr, DIM, 0, 0, wq, DIM, 0, 0, q, DIM, 0, 0, bq, DIM, 0};
                gemm_std<64, false, true><<<dim3(8, 32, 1), 256, SMEM64>>>(gq);
                cudaStreamWaitEvent(0, res.eL[l], 0);
                kuse = kca + (size_t)l * XSZ;
                vtuse = vtca + (size_t)l * XSZ;
            }

            SSP sp{q, kuse, tok, S, causal};
            scores_softmax<<<dim3(16, BB * NH), 256, SS_SMEM_BYTES>>>(sp);

            GP gp;
            gp = GP{S, LDQ, NH * LL, LL, vtuse, M, LDQ, 64LL * M, ctxp, DIM, LL, 64,
                    nullptr, 512, 0};
            gemm_std<64, true, true><<<dim3(1, 4, BB * NH), 256, SMEM64>>>(gp);
            // fused out-proj + residual + LN (cluster of 8 column blocks)
            GLP gl{ctxp, wo, bo, x, gg, bt, x, xr, DIM};
            gemm_ln<<<dim3(8, 32), 256, GLN_SMEM>>>(gl);
        }

        // FFN
        GP gp;
        gp = GP{xr, DIM, 0, 0, w1r + (size_t)l * FFD * DIM, DIM, 0, 0,
                ffh, FFD, 0, 0, ffn_b1 + (size_t)l * FFD, DIM, 1};
        gemm_std<128, false, true><<<dim3(16, 32, 1), 256, SMEM128>>>(gp);
        float* lnout = (l == NLAY - 1) ? out : x;
        GLP gl{ffh, w2r + (size_t)l * DIM * FFD, ffn_b2 + bofs, x,
               ffn_g + bofs, ffn_bb + bofs, lnout, xr, FFD};
        gemm_ln<<<dim3(8, 32), 256, GLN_SMEM>>>(gl);
    }
}